// round 13
// baseline (speedup 1.0000x reference)
#include <cuda_runtime.h>
#include <cuda_bf16.h>
#include <float.h>
#include <stdint.h>

#define Bb 2
#define Ss 2048
#define Dd 768
#define Hh 12
#define DH 64
#define Mm (Bb*Ss)

// ---------------- scratch ----------------
__device__ float g_Q[(size_t)Bb*Hh*Ss*DH];
__device__ float g_K[(size_t)Bb*Hh*Ss*DH];
__device__ float g_V[(size_t)Bb*Hh*Ss*DH];
__device__ __nv_bfloat16 g_Oh[(size_t)Mm*Dd];
__device__ __nv_bfloat16 g_Ol[(size_t)Mm*Dd];
__device__ float g_Xt[(size_t)Mm*Dd];              // tf32-rounded X
__device__ float g_Wt[3][(size_t)Dd*Dd];           // tf32-rounded Wq/Wk/Wv
__device__ __nv_bfloat16 g_Woh[(size_t)Dd*Dd];     // Wo bf16 hi
__device__ __nv_bfloat16 g_Wol[(size_t)Dd*Dd];     // Wo bf16 lo

// ---------------- helpers ----------------
__device__ __forceinline__ uint32_t smem_u32(const void* p) {
    uint32_t a;
    asm("{ .reg .u64 t; cvta.to.shared.u64 t, %1; cvt.u32.u64 %0, t; }" : "=r"(a) : "l"(p));
    return a;
}
__device__ __forceinline__ void cp16(uint32_t dst, const void* src) {
    asm volatile("cp.async.cg.shared.global [%0], [%1], 16;"
        :: "r"(dst), "l"(__cvta_generic_to_global(src)));
}
__device__ __forceinline__ void cp_commit() { asm volatile("cp.async.commit_group;"); }
__device__ __forceinline__ void cp_wait0()  { asm volatile("cp.async.wait_group 0;"); }

__device__ __forceinline__ float to_tf32(float x) {
    uint32_t u;
    asm("cvt.rna.tf32.f32 %0, %1;" : "=r"(u) : "f"(x));
    return __uint_as_float(u);
}
__device__ __forceinline__ uint32_t f2u(float x) { return __float_as_uint(x); }

// tf32 k8 MMA
__device__ __forceinline__ void mma8(float* d, const uint32_t* a, const uint32_t* b) {
    asm volatile("mma.sync.aligned.m16n8k8.row.col.f32.tf32.tf32.f32 "
        "{%0,%1,%2,%3}, {%4,%5,%6,%7}, {%8,%9}, {%0,%1,%2,%3};"
        : "+f"(d[0]), "+f"(d[1]), "+f"(d[2]), "+f"(d[3])
        : "r"(a[0]), "r"(a[1]), "r"(a[2]), "r"(a[3]), "r"(b[0]), "r"(b[1]));
}
// bf16 k16 MMA (out-projection)
__device__ __forceinline__ void mma16(float* d, const uint32_t* a, const uint32_t* b) {
    asm volatile("mma.sync.aligned.m16n8k16.row.col.f32.bf16.bf16.f32 "
        "{%0,%1,%2,%3}, {%4,%5,%6,%7}, {%8,%9}, {%0,%1,%2,%3};"
        : "+f"(d[0]), "+f"(d[1]), "+f"(d[2]), "+f"(d[3])
        : "r"(a[0]), "r"(a[1]), "r"(a[2]), "r"(a[3]), "r"(b[0]), "r"(b[1]));
}
__device__ __forceinline__ void ldm4(uint32_t* r, uint32_t addr) {
    asm volatile("ldmatrix.sync.aligned.m8n8.x4.shared.b16 {%0,%1,%2,%3}, [%4];"
        : "=r"(r[0]), "=r"(r[1]), "=r"(r[2]), "=r"(r[3]) : "r"(addr));
}
__device__ __forceinline__ void decb(float x, __nv_bfloat16& h, __nv_bfloat16& l) {
    h = __float2bfloat16_rn(x);
    l = __float2bfloat16_rn(x - __bfloat162float(h));
}

// ---------------- pre-pass ----------------
__global__ void conv_all(const float* __restrict__ x,
                         const float* __restrict__ wq, const float* __restrict__ wk,
                         const float* __restrict__ wv, const float* __restrict__ wo) {
    int i = blockIdx.x * blockDim.x + threadIdx.x;
    int stride = gridDim.x * blockDim.x;
    for (int t = i; t < Mm * Dd; t += stride) g_Xt[t] = to_tf32(x[t]);
    const float* ws[3] = {wq, wk, wv};
    for (int z = 0; z < 3; z++)
        for (int t = i; t < Dd * Dd; t += stride) g_Wt[z][t] = to_tf32(ws[z][t]);
    for (int t = i; t < Dd * Dd; t += stride) decb(wo[t], g_Woh[t], g_Wol[t]);
}

// ============================================================================
// QKV GEMM, 1xtf32 (unchanged from R12)
// ============================================================================
#define TSTG_B 27648
#define TOFF_B 18432
#define GCH32 24

__global__ __launch_bounds__(256, 3) void gemm_qkv_tf() {
    extern __shared__ char smc[];
    const int tid = threadIdx.x;
    const int lane = tid & 31;
    const int wid = tid >> 5;
    const int wm = wid >> 1, wn = wid & 1;
    const int z = blockIdx.z;
    const int mBase = blockIdx.x * 128, nBase = blockIdx.y * 64;

    float* Obuf = (z == 0) ? g_Q : (z == 1 ? g_K : g_V);
    const float scale = (z == 0) ? 0.125f : 1.0f;
    const float* A = g_Xt + (size_t)mBase * Dd;
    const float* B = g_Wt[z] + (size_t)nBase * Dd;

    uint32_t sb = smem_u32(smc);

    float acc[2][4][4];
    #pragma unroll
    for (int mt = 0; mt < 2; mt++)
        #pragma unroll
        for (int nt = 0; nt < 4; nt++)
            #pragma unroll
            for (int q = 0; q < 4; q++) acc[mt][nt][q] = 0.f;

    uint32_t soA[4]; size_t goA[4];
    #pragma unroll
    for (int t = 0; t < 4; t++) {
        int idx = t * 256 + tid;
        int r = idx >> 3, s = idx & 7;
        soA[t] = (uint32_t)(r * 144 + s * 16);
        goA[t] = (size_t)r * Dd + s * 4;
    }
    uint32_t soB[2]; size_t goB[2];
    #pragma unroll
    for (int t = 0; t < 2; t++) {
        int idx = t * 256 + tid;
        int r = idx >> 3, s = idx & 7;
        soB[t] = (uint32_t)(r * 144 + s * 16);
        goB[t] = (size_t)r * Dd + s * 4;
    }

    const int arow = ((lane >> 3) & 1) * 8 + (lane & 7);
    const uint32_t acolb = (uint32_t)((lane >> 4) * 16);
    const uint32_t aoff0 = (uint32_t)((wm * 32 + arow) * 144) + acolb;
    const uint32_t aoff1 = aoff0 + 16 * 144;
    const int brow = ((lane >> 4) << 3) + (lane & 7);
    const uint32_t bcolb = (uint32_t)(((lane >> 3) & 1) * 16);
    uint32_t boff[2];
    #pragma unroll
    for (int p = 0; p < 2; p++)
        boff[p] = (uint32_t)((wn * 32 + p * 16 + brow) * 144) + bcolb;

    auto load_chunk = [&](int c, int stage) {
        uint32_t st = sb + stage * TSTG_B;
        const size_t kq = (size_t)c * 32;
        #pragma unroll
        for (int t = 0; t < 4; t++) cp16(st + soA[t], A + goA[t] + kq);
        #pragma unroll
        for (int t = 0; t < 2; t++) cp16(st + TOFF_B + soB[t], B + goB[t] + kq);
        cp_commit();
    };

    load_chunk(0, 0);

    for (int c = 0; c < GCH32; c++) {
        cp_wait0();
        __syncthreads();
        if (c + 1 < GCH32) load_chunk(c + 1, (c + 1) & 1);

        const uint32_t st = sb + (c & 1) * TSTG_B;
        #pragma unroll
        for (int ks = 0; ks < 4; ks++) {
            const uint32_t kb = (uint32_t)(ks * 32);
            uint32_t a0[4], a1[4], b0[4], b1[4];
            ldm4(a0, st + aoff0 + kb);
            ldm4(a1, st + aoff1 + kb);
            ldm4(b0, st + TOFF_B + boff[0] + kb);
            ldm4(b1, st + TOFF_B + boff[1] + kb);
            mma8(acc[0][0], a0, b0);
            mma8(acc[1][0], a1, b0);
            mma8(acc[0][1], a0, b0 + 2);
            mma8(acc[1][1], a1, b0 + 2);
            mma8(acc[0][2], a0, b1);
            mma8(acc[1][2], a1, b1);
            mma8(acc[0][3], a0, b1 + 2);
            mma8(acc[1][3], a1, b1 + 2);
        }
    }

    #pragma unroll
    for (int mt = 0; mt < 2; mt++) {
        int r0 = mBase + wm * 32 + mt * 16 + (lane >> 2);
        #pragma unroll
        for (int half = 0; half < 2; half++) {
            int row = r0 + half * 8;
            int bb = row >> 11, ssi = row & 2047;
            #pragma unroll
            for (int nt = 0; nt < 4; nt++) {
                int colg = nBase + wn * 32 + nt * 8 + 2 * (lane & 3);
                int h = colg >> 6, dh = colg & 63;
                float* dst = Obuf + (((size_t)bb * Hh + h) * Ss + ssi) * DH + dh;
                *(float2*)dst = make_float2(
                    to_tf32(acc[mt][nt][half * 2 + 0] * scale),
                    to_tf32(acc[mt][nt][half * 2 + 1] * scale));
            }
        }
    }
}

// ---------------- bf16x3 GEMM core (out-projection, unchanged) ----------------
#define GSTG_B 30720
#define OFF_AL 10240
#define OFF_BH 20480
#define OFF_BL 25600

__device__ __forceinline__ void gemm_core_bf3(const __nv_bfloat16* __restrict__ Ah,
                                              const __nv_bfloat16* __restrict__ Al,
                                              const __nv_bfloat16* __restrict__ Bh,
                                              const __nv_bfloat16* __restrict__ Bl,
                                              char* smc, float acc[2][4][4]) {
    const int tid = threadIdx.x;
    const int lane = tid & 31;
    const int wid = tid >> 5;
    const int wm = wid >> 1, wn = wid & 1;

    uint32_t sb = smem_u32(smc);

    #pragma unroll
    for (int mt = 0; mt < 2; mt++)
        #pragma unroll
        for (int nt = 0; nt < 4; nt++)
            #pragma unroll
            for (int q = 0; q < 4; q++) acc[mt][nt][q] = 0.f;

    const int ra0 = tid >> 2, sa = tid & 3;
    const int ra1 = (256 + tid) >> 2;
    const uint32_t soA0 = (uint32_t)(ra0 * 80 + sa * 16);
    const uint32_t soA1 = (uint32_t)(ra1 * 80 + sa * 16);
    const size_t goA0 = (size_t)ra0 * Dd + sa * 8;
    const size_t goA1 = (size_t)ra1 * Dd + sa * 8;
    const uint32_t soB0 = soA0;
    const size_t goB0 = goA0;

    const int arow = lane & 15, acolb = ((lane >> 4) << 4);
    const uint32_t aoff0 = (uint32_t)((wm * 32 + arow) * 80) + acolb;
    const uint32_t aoff1 = aoff0 + 16 * 80;
    const int brow = ((lane >> 4) << 3) + (lane & 7);
    const int bcolb = (((lane >> 3) & 1) << 4);
    uint32_t boff[2];
    #pragma unroll
    for (int p = 0; p < 2; p++)
        boff[p] = (uint32_t)((wn * 32 + p * 16 + brow) * 80) + bcolb;

    auto load_chunk = [&](int c, int stage) {
        uint32_t st = sb + stage * GSTG_B;
        const size_t kq = (size_t)c * 32;
        cp16(st + soA0,          Ah + goA0 + kq);
        cp16(st + soA1,          Ah + goA1 + kq);
        cp16(st + OFF_AL + soA0, Al + goA0 + kq);
        cp16(st + OFF_AL + soA1, Al + goA1 + kq);
        cp16(st + OFF_BH + soB0, Bh + goB0 + kq);
        cp16(st + OFF_BL + soB0, Bl + goB0 + kq);
        cp_commit();
    };

    load_chunk(0, 0);

    for (int c = 0; c < GCH32; c++) {
        cp_wait0();
        __syncthreads();
        if (c + 1 < GCH32) load_chunk(c + 1, (c + 1) & 1);

        const uint32_t st = sb + (c & 1) * GSTG_B;
        #pragma unroll
        for (int kh = 0; kh < 2; kh++) {
            const uint32_t ko = kh * 32;
            const uint32_t stA  = st + ko,           stAl = st + OFF_AL + ko;
            const uint32_t stB  = st + OFF_BH + ko,  stBl = st + OFF_BL + ko;

            uint32_t ah[2][4], al[2][4];
            ldm4(ah[0], stA  + aoff0);
            ldm4(ah[1], stA  + aoff1);
            ldm4(al[0], stAl + aoff0);
            ldm4(al[1], stAl + aoff1);

            uint32_t bh[2][4], bl[2][4];
            ldm4(bh[0], stB  + boff[0]);
            ldm4(bl[0], stBl + boff[0]);
            #pragma unroll
            for (int p = 0; p < 2; p++) {
                const int cur = p & 1, nxt = cur ^ 1;
                if (p < 1) {
                    ldm4(bh[nxt], stB  + boff[1]);
                    ldm4(bl[nxt], stBl + boff[1]);
                }
                #pragma unroll
                for (int j = 0; j < 2; j++)
                    #pragma unroll
                    for (int mt = 0; mt < 2; mt++)
                        mma16(acc[mt][p * 2 + j], al[mt], &bh[cur][2 * j]);
                #pragma unroll
                for (int j = 0; j < 2; j++)
                    #pragma unroll
                    for (int mt = 0; mt < 2; mt++)
                        mma16(acc[mt][p * 2 + j], ah[mt], &bl[cur][2 * j]);
                #pragma unroll
                for (int j = 0; j < 2; j++)
                    #pragma unroll
                    for (int mt = 0; mt < 2; mt++)
                        mma16(acc[mt][p * 2 + j], ah[mt], &bh[cur][2 * j]);
            }
        }
    }
}

__global__ __launch_bounds__(256, 3) void gemm_out_tc(float* __restrict__ C) {
    extern __shared__ char smc[];
    const int mBase = blockIdx.x * 128, nBase = blockIdx.y * 64;

    float acc[2][4][4];
    gemm_core_bf3(g_Oh + (size_t)mBase * Dd, g_Ol + (size_t)mBase * Dd,
                  g_Woh + (size_t)nBase * Dd, g_Wol + (size_t)nBase * Dd,
                  smc, acc);

    const int lane = threadIdx.x & 31, wid = threadIdx.x >> 5;
    const int wm = wid >> 1, wn = wid & 1;
    #pragma unroll
    for (int mt = 0; mt < 2; mt++) {
        int r0 = mBase + wm * 32 + mt * 16 + (lane >> 2);
        #pragma unroll
        for (int half = 0; half < 2; half++) {
            int row = r0 + half * 8;
            float* dst = C + (size_t)row * Dd + nBase + wn * 32;
            #pragma unroll
            for (int nt = 0; nt < 4; nt++) {
                int d = nt * 8 + 2 * (lane & 3);
                *(float2*)(dst + d) = make_float2(acc[mt][nt][half * 2 + 0],
                                                  acc[mt][nt][half * 2 + 1]);
            }
        }
    }
}

// ============================================================================
// Flash attention: 256 threads, 8 warps x 16 Q-rows, SAME smem (2 CTAs/SM).
// Qs[128][68] | Ks[64][68] | Vs[64][72] | Ps[128][72]
// ============================================================================
#define QS_OFF 0
#define KS_OFF 8704
#define VS_OFF 13056
#define PS_OFF 17664

__global__ __launch_bounds__(256, 2) void attn_mma() {
    extern __shared__ float sm[];
    float* Qs = sm + QS_OFF;
    float* Ks = sm + KS_OFF;
    float* Vs = sm + VS_OFF;
    float* Ps = sm + PS_OFF;

    const int tid = threadIdx.x;
    const int lane = tid & 31, wid = tid >> 5;   // wid 0..7
    const int qt = gridDim.x - 1 - blockIdx.x;   // heavy tiles first
    const int h = blockIdx.y, b = blockIdx.z;

    const float* Qg = g_Q + (((size_t)b * Hh + h) * Ss + (size_t)qt * 128) * DH;
    const float* Kg = g_K + (((size_t)b * Hh + h) * Ss) * DH;
    const float* Vg = g_V + (((size_t)b * Hh + h) * Ss) * DH;

    uint32_t sQ = smem_u32(Qs), sK = smem_u32(Ks), sV = smem_u32(Vs);

    // Q tile load: 2048 segs / 256 thr = 8 each
    #pragma unroll
    for (int t = 0; t < 8; t++) {
        int idx = tid + t * 256;
        int r = idx >> 4, c = (idx & 15) * 4;
        cp16(sQ + (r * 68 + c) * 4, Qg + r * DH + c);
    }
    cp_commit();

    float o[8][4];
    float mrow[2], lrow[2];
    mrow[0] = mrow[1] = -1e30f;
    lrow[0] = lrow[1] = 0.f;
    #pragma unroll
    for (int nt = 0; nt < 8; nt++)
        #pragma unroll
        for (int q = 0; q < 4; q++) o[nt][q] = 0.f;

    const int cL = lane & 3, rL = lane >> 2;
    const int ktMax = 2 * qt + 1;

    for (int kt = 0; kt <= ktMax; kt++) {
        __syncthreads();      // prev-iter K/V consumers done (and Qs ready, iter 0)
        const float* Kp = Kg + (size_t)kt * 64 * DH;
        const float* Vp = Vg + (size_t)kt * 64 * DH;
        // K/V loads: 1024 segs each / 256 thr = 4 each
        #pragma unroll
        for (int t = 0; t < 4; t++) {
            int idx = tid + t * 256;
            int r = idx >> 4, c = (idx & 15) * 4;
            cp16(sK + (r * 68 + c) * 4, Kp + r * DH + c);
            cp16(sV + (r * 72 + c) * 4, Vp + r * DH + c);
        }
        cp_commit();
        cp_wait0();
        __syncthreads();

        // S = Q K^T : warp rows wid*16..+15, cols 0..63
        float s[8][4];
        #pragma unroll
        for (int nt = 0; nt < 8; nt++)
            #pragma unroll
            for (int q = 0; q < 4; q++) s[nt][q] = 0.f;

        const float* qp = Qs + (wid * 16 + rL) * 68;
        #pragma unroll
        for (int ks = 0; ks < 8; ks++) {
            const int kb = ks * 8 + cL;
            uint32_t a[4];
            a[0] = f2u(qp[kb]);
            a[1] = f2u(qp[8 * 68 + kb]);
            a[2] = f2u(qp[kb + 4]);
            a[3] = f2u(qp[8 * 68 + kb + 4]);
            #pragma unroll
            for (int nt = 0; nt < 8; nt++) {
                const float* kp = Ks + (nt * 8 + rL) * 68;
                uint32_t bfr[2] = { f2u(kp[kb]), f2u(kp[kb + 4]) };
                mma8(s[nt], a, bfr);
            }
        }

        // causal mask
        if (kt >= 2 * qt) {
            int rg0 = qt * 128 + wid * 16 + rL;
            #pragma unroll
            for (int nt = 0; nt < 8; nt++) {
                int cg = kt * 64 + nt * 8 + 2 * cL;
                if (cg     > rg0)     s[nt][0] = -1e30f;
                if (cg + 1 > rg0)     s[nt][1] = -1e30f;
                if (cg     > rg0 + 8) s[nt][2] = -1e30f;
                if (cg + 1 > rg0 + 8) s[nt][3] = -1e30f;
            }
        }

        // online softmax (rows rL, rL+8)
        float v0 = -1e30f, v1 = -1e30f;
        #pragma unroll
        for (int nt = 0; nt < 8; nt++) {
            v0 = fmaxf(v0, fmaxf(s[nt][0], s[nt][1]));
            v1 = fmaxf(v1, fmaxf(s[nt][2], s[nt][3]));
        }
        v0 = fmaxf(v0, __shfl_xor_sync(0xffffffffu, v0, 1));
        v0 = fmaxf(v0, __shfl_xor_sync(0xffffffffu, v0, 2));
        v1 = fmaxf(v1, __shfl_xor_sync(0xffffffffu, v1, 1));
        v1 = fmaxf(v1, __shfl_xor_sync(0xffffffffu, v1, 2));

        float mn0 = fmaxf(mrow[0], v0);
        float mn1 = fmaxf(mrow[1], v1);
        float cr0 = __expf(mrow[0] - mn0);
        float cr1 = __expf(mrow[1] - mn1);
        mrow[0] = mn0; mrow[1] = mn1;

        float rs0 = 0.f, rs1 = 0.f;
        float* prow0 = Ps + (wid * 16 + rL) * 72;
        float* prow1 = prow0 + 8 * 72;
        #pragma unroll
        for (int nt = 0; nt < 8; nt++) {
            float p0 = __expf(s[nt][0] - mn0);
            float p1 = __expf(s[nt][1] - mn0);
            float p2 = __expf(s[nt][2] - mn1);
            float p3 = __expf(s[nt][3] - mn1);
            rs0 += p0 + p1; rs1 += p2 + p3;
            int cc = nt * 8 + 2 * cL;
            *(float2*)(prow0 + cc) = make_float2(to_tf32(p0), to_tf32(p1));
            *(float2*)(prow1 + cc) = make_float2(to_tf32(p2), to_tf32(p3));
        }
        rs0 += __shfl_xor_sync(0xffffffffu, rs0, 1);
        rs0 += __shfl_xor_sync(0xffffffffu, rs0, 2);
        rs1 += __shfl_xor_sync(0xffffffffu, rs1, 1);
        rs1 += __shfl_xor_sync(0xffffffffu, rs1, 2);
        lrow[0] = lrow[0] * cr0 + rs0;
        lrow[1] = lrow[1] * cr1 + rs1;
        #pragma unroll
        for (int nt = 0; nt < 8; nt++) {
            o[nt][0] *= cr0; o[nt][1] *= cr0;
            o[nt][2] *= cr1; o[nt][3] *= cr1;
        }
        __syncwarp();    // own warp's P rows visible before PV

        // O += P V
        const float* pp = Ps + (wid * 16 + rL) * 72;
        #pragma unroll
        for (int ks = 0; ks < 8; ks++) {
            const int kb = ks * 8;
            uint32_t a[4];
            a[0] = f2u(pp[kb + cL]);
            a[1] = f2u(pp[8 * 72 + kb + cL]);
            a[2] = f2u(pp[kb + 4 + cL]);
            a[3] = f2u(pp[8 * 72 + kb + 4 + cL]);
            #pragma unroll
            for (int nt = 0; nt < 8; nt++) {
                uint32_t bfr[2] = { f2u(Vs[(kb + cL) * 72 + nt * 8 + rL]),
                                    f2u(Vs[(kb + 4 + cL) * 72 + nt * 8 + rL]) };
                mma8(o[nt], a, bfr);
            }
        }
    }

    // epilogue: normalize, decompose to bf16 hi/lo for the out-projection
    float inv0 = 1.f / lrow[0];
    float inv1 = 1.f / lrow[1];
    int r0 = qt * 128 + wid * 16 + rL;
    size_t base0 = ((size_t)b * Ss + r0) * Dd + h * DH;
    size_t base1 = base0 + 8 * Dd;
    #pragma unroll
    for (int nt = 0; nt < 8; nt++) {
        int cc = nt * 8 + 2 * cL;
        float x0 = o[nt][0] * inv0, x1 = o[nt][1] * inv0;
        float x2 = o[nt][2] * inv1, x3 = o[nt][3] * inv1;
        __nv_bfloat16 h0, l0, h1, l1, h2, l2, h3, l3;
        decb(x0, h0, l0); decb(x1, h1, l1);
        decb(x2, h2, l2); decb(x3, h3, l3);
        *(__nv_bfloat162*)(g_Oh + base0 + cc) = __nv_bfloat162(h0, h1);
        *(__nv_bfloat162*)(g_Ol + base0 + cc) = __nv_bfloat162(l0, l1);
        *(__nv_bfloat162*)(g_Oh + base1 + cc) = __nv_bfloat162(h2, h3);
        *(__nv_bfloat162*)(g_Ol + base1 + cc) = __nv_bfloat162(l2, l3);
    }
}

// ---------------------------------------------------------------------------

extern "C" void kernel_launch(void* const* d_in, const int* in_sizes, int n_in,
                              void* d_out, int out_size)
{
    const float* x  = (const float*)d_in[0];
    const float* Wq = (const float*)d_in[1];
    const float* Wk = (const float*)d_in[2];
    const float* Wv = (const float*)d_in[3];
    const float* Wo = (const float*)d_in[4];
    float* out = (float*)d_out;

    const int QKV_SMEM  = 2 * TSTG_B;                          // 55296
    const int GEMM_SMEM = 2 * GSTG_B;                          // 61440
    const int ATTN_SMEM = (PS_OFF + 128 * 72) * (int)sizeof(float);  // 107520

    cudaFuncSetAttribute(gemm_qkv_tf, cudaFuncAttributeMaxDynamicSharedMemorySize, QKV_SMEM);
    cudaFuncSetAttribute(gemm_out_tc, cudaFuncAttributeMaxDynamicSharedMemorySize, GEMM_SMEM);
    cudaFuncSetAttribute(attn_mma,    cudaFuncAttributeMaxDynamicSharedMemorySize, ATTN_SMEM);

    conv_all<<<512, 256>>>(x, Wq, Wk, Wv, Wo);
    gemm_qkv_tf<<<dim3(Mm / 128, Dd / 64, 3), 256, QKV_SMEM>>>();
    attn_mma<<<dim3(Ss / 128, Hh, Bb), 256, ATTN_SMEM>>>();
    gemm_out_tc<<<dim3(Mm / 128, Dd / 64), 256, GEMM_SMEM>>>(out);
}

// round 14
// speedup vs baseline: 1.1476x; 1.1476x over previous
#include <cuda_runtime.h>
#include <cuda_bf16.h>
#include <float.h>
#include <stdint.h>

#define Bb 2
#define Ss 2048
#define Dd 768
#define Hh 12
#define DH 64
#define Mm (Bb*Ss)

// ---------------- scratch ----------------
__device__ float g_Q[(size_t)Bb*Hh*Ss*DH];
__device__ float g_K[(size_t)Bb*Hh*Ss*DH];
__device__ float g_V[(size_t)Bb*Hh*Ss*DH];
__device__ float g_Ot[(size_t)Mm*Dd];              // attention out, tf32-rounded
__device__ float g_Xt[(size_t)Mm*Dd];              // tf32-rounded X
__device__ float g_Wt[3][(size_t)Dd*Dd];           // tf32-rounded Wq/Wk/Wv
__device__ float g_Wot[(size_t)Dd*Dd];             // tf32-rounded Wo

// ---------------- helpers ----------------
__device__ __forceinline__ uint32_t smem_u32(const void* p) {
    uint32_t a;
    asm("{ .reg .u64 t; cvta.to.shared.u64 t, %1; cvt.u32.u64 %0, t; }" : "=r"(a) : "l"(p));
    return a;
}
__device__ __forceinline__ void cp16(uint32_t dst, const void* src) {
    asm volatile("cp.async.cg.shared.global [%0], [%1], 16;"
        :: "r"(dst), "l"(__cvta_generic_to_global(src)));
}
__device__ __forceinline__ void cp_commit() { asm volatile("cp.async.commit_group;"); }
__device__ __forceinline__ void cp_wait0()  { asm volatile("cp.async.wait_group 0;"); }

__device__ __forceinline__ float to_tf32(float x) {
    uint32_t u;
    asm("cvt.rna.tf32.f32 %0, %1;" : "=r"(u) : "f"(x));
    return __uint_as_float(u);
}
__device__ __forceinline__ uint32_t f2u(float x) { return __float_as_uint(x); }

// tf32 k8 MMA
__device__ __forceinline__ void mma8(float* d, const uint32_t* a, const uint32_t* b) {
    asm volatile("mma.sync.aligned.m16n8k8.row.col.f32.tf32.tf32.f32 "
        "{%0,%1,%2,%3}, {%4,%5,%6,%7}, {%8,%9}, {%0,%1,%2,%3};"
        : "+f"(d[0]), "+f"(d[1]), "+f"(d[2]), "+f"(d[3])
        : "r"(a[0]), "r"(a[1]), "r"(a[2]), "r"(a[3]), "r"(b[0]), "r"(b[1]));
}
__device__ __forceinline__ void ldm4(uint32_t* r, uint32_t addr) {
    asm volatile("ldmatrix.sync.aligned.m8n8.x4.shared.b16 {%0,%1,%2,%3}, [%4];"
        : "=r"(r[0]), "=r"(r[1]), "=r"(r[2]), "=r"(r[3]) : "r"(addr));
}

// ---------------- pre-pass ----------------
__global__ void conv_all(const float* __restrict__ x,
                         const float* __restrict__ wq, const float* __restrict__ wk,
                         const float* __restrict__ wv, const float* __restrict__ wo) {
    int i = blockIdx.x * blockDim.x + threadIdx.x;
    int stride = gridDim.x * blockDim.x;
    for (int t = i; t < Mm * Dd; t += stride) g_Xt[t] = to_tf32(x[t]);
    const float* ws[3] = {wq, wk, wv};
    for (int z = 0; z < 3; z++)
        for (int t = i; t < Dd * Dd; t += stride) g_Wt[z][t] = to_tf32(ws[z][t]);
    for (int t = i; t < Dd * Dd; t += stride) g_Wot[t] = to_tf32(wo[t]);
}

// ============================================================================
// 1xtf32 GEMM core: CTA 128x64, BK=32, 2-stage, 3 CTAs/SM, 256 threads.
// 8 warps (wm 0..3 x 32 rows, wn 0..1 x 32 cols), warp tile 32x32.
// Stage (bytes): A[128 rows][144 B] = 18432 | B[64][144] = 9216 -> 27648.
// ============================================================================
#define TSTG_B 27648
#define TOFF_B 18432
#define GCH32 24

__device__ __forceinline__ void gemm_core_tf(const float* __restrict__ A,
                                             const float* __restrict__ B,
                                             char* smc, float acc[2][4][4]) {
    const int tid = threadIdx.x;
    const int lane = tid & 31;
    const int wid = tid >> 5;
    const int wm = wid >> 1, wn = wid & 1;

    uint32_t sb = smem_u32(smc);

    #pragma unroll
    for (int mt = 0; mt < 2; mt++)
        #pragma unroll
        for (int nt = 0; nt < 4; nt++)
            #pragma unroll
            for (int q = 0; q < 4; q++) acc[mt][nt][q] = 0.f;

    uint32_t soA[4]; size_t goA[4];
    #pragma unroll
    for (int t = 0; t < 4; t++) {
        int idx = t * 256 + tid;
        int r = idx >> 3, s = idx & 7;
        soA[t] = (uint32_t)(r * 144 + s * 16);
        goA[t] = (size_t)r * Dd + s * 4;
    }
    uint32_t soB[2]; size_t goB[2];
    #pragma unroll
    for (int t = 0; t < 2; t++) {
        int idx = t * 256 + tid;
        int r = idx >> 3, s = idx & 7;
        soB[t] = (uint32_t)(r * 144 + s * 16);
        goB[t] = (size_t)r * Dd + s * 4;
    }

    const int arow = ((lane >> 3) & 1) * 8 + (lane & 7);
    const uint32_t acolb = (uint32_t)((lane >> 4) * 16);
    const uint32_t aoff0 = (uint32_t)((wm * 32 + arow) * 144) + acolb;
    const uint32_t aoff1 = aoff0 + 16 * 144;
    const int brow = ((lane >> 4) << 3) + (lane & 7);
    const uint32_t bcolb = (uint32_t)(((lane >> 3) & 1) * 16);
    uint32_t boff[2];
    #pragma unroll
    for (int p = 0; p < 2; p++)
        boff[p] = (uint32_t)((wn * 32 + p * 16 + brow) * 144) + bcolb;

    auto load_chunk = [&](int c, int stage) {
        uint32_t st = sb + stage * TSTG_B;
        const size_t kq = (size_t)c * 32;
        #pragma unroll
        for (int t = 0; t < 4; t++) cp16(st + soA[t], A + goA[t] + kq);
        #pragma unroll
        for (int t = 0; t < 2; t++) cp16(st + TOFF_B + soB[t], B + goB[t] + kq);
        cp_commit();
    };

    load_chunk(0, 0);

    for (int c = 0; c < GCH32; c++) {
        cp_wait0();
        __syncthreads();
        if (c + 1 < GCH32) load_chunk(c + 1, (c + 1) & 1);

        const uint32_t st = sb + (c & 1) * TSTG_B;
        #pragma unroll
        for (int ks = 0; ks < 4; ks++) {
            const uint32_t kb = (uint32_t)(ks * 32);
            uint32_t a0[4], a1[4], b0[4], b1[4];
            ldm4(a0, st + aoff0 + kb);
            ldm4(a1, st + aoff1 + kb);
            ldm4(b0, st + TOFF_B + boff[0] + kb);
            ldm4(b1, st + TOFF_B + boff[1] + kb);
            mma8(acc[0][0], a0, b0);
            mma8(acc[1][0], a1, b0);
            mma8(acc[0][1], a0, b0 + 2);
            mma8(acc[1][1], a1, b0 + 2);
            mma8(acc[0][2], a0, b1);
            mma8(acc[1][2], a1, b1);
            mma8(acc[0][3], a0, b1 + 2);
            mma8(acc[1][3], a1, b1 + 2);
        }
    }
}

// QKV projection: tf32-rounded scatter into [B,H,S,DH]; Q pre-scaled
__global__ __launch_bounds__(256, 3) void gemm_qkv_tf() {
    extern __shared__ char smc[];
    const int lane = threadIdx.x & 31, wid = threadIdx.x >> 5;
    const int wm = wid >> 1, wn = wid & 1;
    const int z = blockIdx.z;
    const int mBase = blockIdx.x * 128, nBase = blockIdx.y * 64;

    float* Obuf = (z == 0) ? g_Q : (z == 1 ? g_K : g_V);
    const float scale = (z == 0) ? 0.125f : 1.0f;

    float acc[2][4][4];
    gemm_core_tf(g_Xt + (size_t)mBase * Dd, g_Wt[z] + (size_t)nBase * Dd, smc, acc);

    #pragma unroll
    for (int mt = 0; mt < 2; mt++) {
        int r0 = mBase + wm * 32 + mt * 16 + (lane >> 2);
        #pragma unroll
        for (int half = 0; half < 2; half++) {
            int row = r0 + half * 8;
            int bb = row >> 11, ssi = row & 2047;
            #pragma unroll
            for (int nt = 0; nt < 4; nt++) {
                int colg = nBase + wn * 32 + nt * 8 + 2 * (lane & 3);
                int h = colg >> 6, dh = colg & 63;
                float* dst = Obuf + (((size_t)bb * Hh + h) * Ss + ssi) * DH + dh;
                *(float2*)dst = make_float2(
                    to_tf32(acc[mt][nt][half * 2 + 0] * scale),
                    to_tf32(acc[mt][nt][half * 2 + 1] * scale));
            }
        }
    }
}

// Output projection (1xtf32): plain fp32 store to d_out
__global__ __launch_bounds__(256, 3) void gemm_out_tf(float* __restrict__ C) {
    extern __shared__ char smc[];
    const int lane = threadIdx.x & 31, wid = threadIdx.x >> 5;
    const int wm = wid >> 1, wn = wid & 1;
    const int mBase = blockIdx.x * 128, nBase = blockIdx.y * 64;

    float acc[2][4][4];
    gemm_core_tf(g_Ot + (size_t)mBase * Dd, g_Wot + (size_t)nBase * Dd, smc, acc);

    #pragma unroll
    for (int mt = 0; mt < 2; mt++) {
        int r0 = mBase + wm * 32 + mt * 16 + (lane >> 2);
        #pragma unroll
        for (int half = 0; half < 2; half++) {
            int row = r0 + half * 8;
            float* dst = C + (size_t)row * Dd + nBase + wn * 32;
            #pragma unroll
            for (int nt = 0; nt < 4; nt++) {
                int d = nt * 8 + 2 * (lane & 3);
                *(float2*)(dst + d) = make_float2(acc[mt][nt][half * 2 + 0],
                                                  acc[mt][nt][half * 2 + 1]);
            }
        }
    }
}

// ============================================================================
// Flash attention (proven R12 config: 128 threads, 4 warps x 32 rows, 2 CTAs/SM)
// Qs[128][68] | Ks[64][68] | Vs[64][72] | Ps[128][72]
// ============================================================================
#define QS_OFF 0
#define KS_OFF 8704
#define VS_OFF 13056
#define PS_OFF 17664

__global__ __launch_bounds__(128) void attn_mma() {
    extern __shared__ float sm[];
    float* Qs = sm + QS_OFF;
    float* Ks = sm + KS_OFF;
    float* Vs = sm + VS_OFF;
    float* Ps = sm + PS_OFF;

    const int tid = threadIdx.x;
    const int lane = tid & 31, wid = tid >> 5;
    const int qt = gridDim.x - 1 - blockIdx.x;
    const int h = blockIdx.y, b = blockIdx.z;

    const float* Qg = g_Q + (((size_t)b * Hh + h) * Ss + (size_t)qt * 128) * DH;
    const float* Kg = g_K + (((size_t)b * Hh + h) * Ss) * DH;
    const float* Vg = g_V + (((size_t)b * Hh + h) * Ss) * DH;

    uint32_t sQ = smem_u32(Qs), sK = smem_u32(Ks), sV = smem_u32(Vs);

    #pragma unroll
    for (int t = 0; t < 16; t++) {
        int idx = tid + t * 128;
        int r = idx >> 4, c = (idx & 15) * 4;
        cp16(sQ + (r * 68 + c) * 4, Qg + r * DH + c);
    }
    cp_commit();

    float o[2][8][4];
    float mrow[2][2], lrow[2][2];
    #pragma unroll
    for (int mt = 0; mt < 2; mt++) {
        mrow[mt][0] = mrow[mt][1] = -1e30f;
        lrow[mt][0] = lrow[mt][1] = 0.f;
        #pragma unroll
        for (int nt = 0; nt < 8; nt++)
            #pragma unroll
            for (int q = 0; q < 4; q++) o[mt][nt][q] = 0.f;
    }

    const int cL = lane & 3, rL = lane >> 2;
    const int ktMax = 2 * qt + 1;

    for (int kt = 0; kt <= ktMax; kt++) {
        __syncthreads();
        const float* Kp = Kg + (size_t)kt * 64 * DH;
        const float* Vp = Vg + (size_t)kt * 64 * DH;
        #pragma unroll
        for (int t = 0; t < 8; t++) {
            int idx = tid + t * 128;
            int r = idx >> 4, c = (idx & 15) * 4;
            cp16(sK + (r * 68 + c) * 4, Kp + r * DH + c);
            cp16(sV + (r * 72 + c) * 4, Vp + r * DH + c);
        }
        cp_commit();
        cp_wait0();
        __syncthreads();

        float s[2][8][4];
        #pragma unroll
        for (int mt = 0; mt < 2; mt++)
            #pragma unroll
            for (int nt = 0; nt < 8; nt++)
                #pragma unroll
                for (int q = 0; q < 4; q++) s[mt][nt][q] = 0.f;

        #pragma unroll
        for (int ks = 0; ks < 8; ks++) {
            const int kb = ks * 8 + cL;
            uint32_t bfr[8][2];
            #pragma unroll
            for (int nt = 0; nt < 8; nt++) {
                const float* kp = Ks + (nt * 8 + rL) * 68;
                bfr[nt][0] = f2u(kp[kb]);
                bfr[nt][1] = f2u(kp[kb + 4]);
            }
            #pragma unroll
            for (int mt = 0; mt < 2; mt++) {
                const float* qp = Qs + (wid * 32 + mt * 16 + rL) * 68;
                uint32_t a[4];
                a[0] = f2u(qp[kb]);
                a[1] = f2u(qp[8 * 68 + kb]);
                a[2] = f2u(qp[kb + 4]);
                a[3] = f2u(qp[8 * 68 + kb + 4]);
                #pragma unroll
                for (int nt = 0; nt < 8; nt++) mma8(s[mt][nt], a, bfr[nt]);
            }
        }

        if (kt >= 2 * qt) {
            #pragma unroll
            for (int mt = 0; mt < 2; mt++) {
                int rg0 = qt * 128 + wid * 32 + mt * 16 + rL;
                #pragma unroll
                for (int nt = 0; nt < 8; nt++) {
                    int cg = kt * 64 + nt * 8 + 2 * cL;
                    if (cg     > rg0)     s[mt][nt][0] = -1e30f;
                    if (cg + 1 > rg0)     s[mt][nt][1] = -1e30f;
                    if (cg     > rg0 + 8) s[mt][nt][2] = -1e30f;
                    if (cg + 1 > rg0 + 8) s[mt][nt][3] = -1e30f;
                }
            }
        }

        #pragma unroll
        for (int mt = 0; mt < 2; mt++) {
            float v0 = -1e30f, v1 = -1e30f;
            #pragma unroll
            for (int nt = 0; nt < 8; nt++) {
                v0 = fmaxf(v0, fmaxf(s[mt][nt][0], s[mt][nt][1]));
                v1 = fmaxf(v1, fmaxf(s[mt][nt][2], s[mt][nt][3]));
            }
            v0 = fmaxf(v0, __shfl_xor_sync(0xffffffffu, v0, 1));
            v0 = fmaxf(v0, __shfl_xor_sync(0xffffffffu, v0, 2));
            v1 = fmaxf(v1, __shfl_xor_sync(0xffffffffu, v1, 1));
            v1 = fmaxf(v1, __shfl_xor_sync(0xffffffffu, v1, 2));

            float mn0 = fmaxf(mrow[mt][0], v0);
            float mn1 = fmaxf(mrow[mt][1], v1);
            float cr0 = __expf(mrow[mt][0] - mn0);
            float cr1 = __expf(mrow[mt][1] - mn1);
            mrow[mt][0] = mn0; mrow[mt][1] = mn1;

            float rs0 = 0.f, rs1 = 0.f;
            float* prow0 = Ps + (wid * 32 + mt * 16 + rL) * 72;
            float* prow1 = prow0 + 8 * 72;
            #pragma unroll
            for (int nt = 0; nt < 8; nt++) {
                float p0 = __expf(s[mt][nt][0] - mn0);
                float p1 = __expf(s[mt][nt][1] - mn0);
                float p2 = __expf(s[mt][nt][2] - mn1);
                float p3 = __expf(s[mt][nt][3] - mn1);
                rs0 += p0 + p1; rs1 += p2 + p3;
                int cc = nt * 8 + 2 * cL;
                *(float2*)(prow0 + cc) = make_float2(to_tf32(p0), to_tf32(p1));
                *(float2*)(prow1 + cc) = make_float2(to_tf32(p2), to_tf32(p3));
            }
            rs0 += __shfl_xor_sync(0xffffffffu, rs0, 1);
            rs0 += __shfl_xor_sync(0xffffffffu, rs0, 2);
            rs1 += __shfl_xor_sync(0xffffffffu, rs1, 1);
            rs1 += __shfl_xor_sync(0xffffffffu, rs1, 2);
            lrow[mt][0] = lrow[mt][0] * cr0 + rs0;
            lrow[mt][1] = lrow[mt][1] * cr1 + rs1;
            #pragma unroll
            for (int nt = 0; nt < 8; nt++) {
                o[mt][nt][0] *= cr0; o[mt][nt][1] *= cr0;
                o[mt][nt][2] *= cr1; o[mt][nt][3] *= cr1;
            }
        }
        __syncwarp();

        #pragma unroll
        for (int ks = 0; ks < 8; ks++) {
            const int kb = ks * 8;
            uint32_t bfr[8][2];
            #pragma unroll
            for (int nt = 0; nt < 8; nt++) {
                bfr[nt][0] = f2u(Vs[(kb + cL) * 72 + nt * 8 + rL]);
                bfr[nt][1] = f2u(Vs[(kb + 4 + cL) * 72 + nt * 8 + rL]);
            }
            #pragma unroll
            for (int mt = 0; mt < 2; mt++) {
                const float* pp = Ps + (wid * 32 + mt * 16 + rL) * 72;
                uint32_t a[4];
                a[0] = f2u(pp[kb + cL]);
                a[1] = f2u(pp[8 * 72 + kb + cL]);
                a[2] = f2u(pp[kb + 4 + cL]);
                a[3] = f2u(pp[8 * 72 + kb + 4 + cL]);
                #pragma unroll
                for (int nt = 0; nt < 8; nt++) mma8(o[mt][nt], a, bfr[nt]);
            }
        }
    }

    // epilogue: normalize, tf32-round, store fp32 to g_Ot [B*S, 768]
    #pragma unroll
    for (int mt = 0; mt < 2; mt++) {
        float inv0 = 1.f / lrow[mt][0];
        float inv1 = 1.f / lrow[mt][1];
        int r0 = qt * 128 + wid * 32 + mt * 16 + rL;
        size_t base0 = ((size_t)b * Ss + r0) * Dd + h * DH;
        size_t base1 = base0 + 8 * Dd;
        #pragma unroll
        for (int nt = 0; nt < 8; nt++) {
            int cc = nt * 8 + 2 * cL;
            *(float2*)(g_Ot + base0 + cc) = make_float2(to_tf32(o[mt][nt][0] * inv0),
                                                        to_tf32(o[mt][nt][1] * inv0));
            *(float2*)(g_Ot + base1 + cc) = make_float2(to_tf32(o[mt][nt][2] * inv1),
                                                        to_tf32(o[mt][nt][3] * inv1));
        }
    }
}

// ---------------------------------------------------------------------------

extern "C" void kernel_launch(void* const* d_in, const int* in_sizes, int n_in,
                              void* d_out, int out_size)
{
    const float* x  = (const float*)d_in[0];
    const float* Wq = (const float*)d_in[1];
    const float* Wk = (const float*)d_in[2];
    const float* Wv = (const float*)d_in[3];
    const float* Wo = (const float*)d_in[4];
    float* out = (float*)d_out;

    const int TF_SMEM   = 2 * TSTG_B;                          // 55296
    const int ATTN_SMEM = (PS_OFF + 128 * 72) * (int)sizeof(float);  // 107520

    cudaFuncSetAttribute(gemm_qkv_tf, cudaFuncAttributeMaxDynamicSharedMemorySize, TF_SMEM);
    cudaFuncSetAttribute(gemm_out_tf, cudaFuncAttributeMaxDynamicSharedMemorySize, TF_SMEM);
    cudaFuncSetAttribute(attn_mma,    cudaFuncAttributeMaxDynamicSharedMemorySize, ATTN_SMEM);

    conv_all<<<512, 256>>>(x, Wq, Wk, Wv, Wo);
    gemm_qkv_tf<<<dim3(Mm / 128, Dd / 64, 3), 256, TF_SMEM>>>();
    attn_mma<<<dim3(Ss / 128, Hh, Bb), 128, ATTN_SMEM>>>();
    gemm_out_tf<<<dim3(Mm / 128, Dd / 64), 256, TF_SMEM>>>(out);
}

// round 15
// speedup vs baseline: 1.1555x; 1.0068x over previous
#include <cuda_runtime.h>
#include <cuda_bf16.h>
#include <float.h>
#include <stdint.h>

#define Bb 2
#define Ss 2048
#define Dd 768
#define Hh 12
#define DH 64
#define Mm (Bb*Ss)

// ---------------- scratch ----------------
__device__ float g_Q[(size_t)Bb*Hh*Ss*DH];
__device__ float g_K[(size_t)Bb*Hh*Ss*DH];
__device__ float g_V[(size_t)Bb*Hh*Ss*DH];
__device__ float g_Ot[(size_t)Mm*Dd];              // attention out, tf32-rounded
__device__ float g_Xt[(size_t)Mm*Dd];              // tf32-rounded X
__device__ float g_Wt[3][(size_t)Dd*Dd];           // tf32-rounded Wq/Wk/Wv
__device__ float g_Wot[(size_t)Dd*Dd];             // tf32-rounded Wo

// ---------------- helpers ----------------
__device__ __forceinline__ uint32_t smem_u32(const void* p) {
    uint32_t a;
    asm("{ .reg .u64 t; cvta.to.shared.u64 t, %1; cvt.u32.u64 %0, t; }" : "=r"(a) : "l"(p));
    return a;
}
__device__ __forceinline__ void cp16(uint32_t dst, const void* src) {
    asm volatile("cp.async.cg.shared.global [%0], [%1], 16;"
        :: "r"(dst), "l"(__cvta_generic_to_global(src)));
}
__device__ __forceinline__ void cp_commit() { asm volatile("cp.async.commit_group;"); }
__device__ __forceinline__ void cp_wait0()  { asm volatile("cp.async.wait_group 0;"); }
__device__ __forceinline__ void cp_wait1()  { asm volatile("cp.async.wait_group 1;"); }

__device__ __forceinline__ float to_tf32(float x) {
    uint32_t u;
    asm("cvt.rna.tf32.f32 %0, %1;" : "=r"(u) : "f"(x));
    return __uint_as_float(u);
}
__device__ __forceinline__ uint32_t f2u(float x) { return __float_as_uint(x); }

// tf32 k8 MMA
__device__ __forceinline__ void mma8(float* d, const uint32_t* a, const uint32_t* b) {
    asm volatile("mma.sync.aligned.m16n8k8.row.col.f32.tf32.tf32.f32 "
        "{%0,%1,%2,%3}, {%4,%5,%6,%7}, {%8,%9}, {%0,%1,%2,%3};"
        : "+f"(d[0]), "+f"(d[1]), "+f"(d[2]), "+f"(d[3])
        : "r"(a[0]), "r"(a[1]), "r"(a[2]), "r"(a[3]), "r"(b[0]), "r"(b[1]));
}
__device__ __forceinline__ void ldm4(uint32_t* r, uint32_t addr) {
    asm volatile("ldmatrix.sync.aligned.m8n8.x4.shared.b16 {%0,%1,%2,%3}, [%4];"
        : "=r"(r[0]), "=r"(r[1]), "=r"(r[2]), "=r"(r[3]) : "r"(addr));
}

// ---------------- pre-pass ----------------
__global__ void conv_all(const float* __restrict__ x,
                         const float* __restrict__ wq, const float* __restrict__ wk,
                         const float* __restrict__ wv, const float* __restrict__ wo) {
    int i = blockIdx.x * blockDim.x + threadIdx.x;
    int stride = gridDim.x * blockDim.x;
    for (int t = i; t < Mm * Dd; t += stride) g_Xt[t] = to_tf32(x[t]);
    const float* ws[3] = {wq, wk, wv};
    for (int z = 0; z < 3; z++)
        for (int t = i; t < Dd * Dd; t += stride) g_Wt[z][t] = to_tf32(ws[z][t]);
    for (int t = i; t < Dd * Dd; t += stride) g_Wot[t] = to_tf32(wo[t]);
}

// ============================================================================
// 1xtf32 GEMM core (unchanged from R14): CTA 128x64, BK=32, 2-stage, 3 CTAs/SM
// ============================================================================
#define TSTG_B 27648
#define TOFF_B 18432
#define GCH32 24

__device__ __forceinline__ void gemm_core_tf(const float* __restrict__ A,
                                             const float* __restrict__ B,
                                             char* smc, float acc[2][4][4]) {
    const int tid = threadIdx.x;
    const int lane = tid & 31;
    const int wid = tid >> 5;
    const int wm = wid >> 1, wn = wid & 1;

    uint32_t sb = smem_u32(smc);

    #pragma unroll
    for (int mt = 0; mt < 2; mt++)
        #pragma unroll
        for (int nt = 0; nt < 4; nt++)
            #pragma unroll
            for (int q = 0; q < 4; q++) acc[mt][nt][q] = 0.f;

    uint32_t soA[4]; size_t goA[4];
    #pragma unroll
    for (int t = 0; t < 4; t++) {
        int idx = t * 256 + tid;
        int r = idx >> 3, s = idx & 7;
        soA[t] = (uint32_t)(r * 144 + s * 16);
        goA[t] = (size_t)r * Dd + s * 4;
    }
    uint32_t soB[2]; size_t goB[2];
    #pragma unroll
    for (int t = 0; t < 2; t++) {
        int idx = t * 256 + tid;
        int r = idx >> 3, s = idx & 7;
        soB[t] = (uint32_t)(r * 144 + s * 16);
        goB[t] = (size_t)r * Dd + s * 4;
    }

    const int arow = ((lane >> 3) & 1) * 8 + (lane & 7);
    const uint32_t acolb = (uint32_t)((lane >> 4) * 16);
    const uint32_t aoff0 = (uint32_t)((wm * 32 + arow) * 144) + acolb;
    const uint32_t aoff1 = aoff0 + 16 * 144;
    const int brow = ((lane >> 4) << 3) + (lane & 7);
    const uint32_t bcolb = (uint32_t)(((lane >> 3) & 1) * 16);
    uint32_t boff[2];
    #pragma unroll
    for (int p = 0; p < 2; p++)
        boff[p] = (uint32_t)((wn * 32 + p * 16 + brow) * 144) + bcolb;

    auto load_chunk = [&](int c, int stage) {
        uint32_t st = sb + stage * TSTG_B;
        const size_t kq = (size_t)c * 32;
        #pragma unroll
        for (int t = 0; t < 4; t++) cp16(st + soA[t], A + goA[t] + kq);
        #pragma unroll
        for (int t = 0; t < 2; t++) cp16(st + TOFF_B + soB[t], B + goB[t] + kq);
        cp_commit();
    };

    load_chunk(0, 0);

    for (int c = 0; c < GCH32; c++) {
        cp_wait0();
        __syncthreads();
        if (c + 1 < GCH32) load_chunk(c + 1, (c + 1) & 1);

        const uint32_t st = sb + (c & 1) * TSTG_B;
        #pragma unroll
        for (int ks = 0; ks < 4; ks++) {
            const uint32_t kb = (uint32_t)(ks * 32);
            uint32_t a0[4], a1[4], b0[4], b1[4];
            ldm4(a0, st + aoff0 + kb);
            ldm4(a1, st + aoff1 + kb);
            ldm4(b0, st + TOFF_B + boff[0] + kb);
            ldm4(b1, st + TOFF_B + boff[1] + kb);
            mma8(acc[0][0], a0, b0);
            mma8(acc[1][0], a1, b0);
            mma8(acc[0][1], a0, b0 + 2);
            mma8(acc[1][1], a1, b0 + 2);
            mma8(acc[0][2], a0, b1);
            mma8(acc[1][2], a1, b1);
            mma8(acc[0][3], a0, b1 + 2);
            mma8(acc[1][3], a1, b1 + 2);
        }
    }
}

// QKV projection: tf32-rounded scatter into [B,H,S,DH]; Q pre-scaled
__global__ __launch_bounds__(256, 3) void gemm_qkv_tf() {
    extern __shared__ char smc[];
    const int lane = threadIdx.x & 31, wid = threadIdx.x >> 5;
    const int wm = wid >> 1, wn = wid & 1;
    const int z = blockIdx.z;
    const int mBase = blockIdx.x * 128, nBase = blockIdx.y * 64;

    float* Obuf = (z == 0) ? g_Q : (z == 1 ? g_K : g_V);
    const float scale = (z == 0) ? 0.125f : 1.0f;

    float acc[2][4][4];
    gemm_core_tf(g_Xt + (size_t)mBase * Dd, g_Wt[z] + (size_t)nBase * Dd, smc, acc);

    #pragma unroll
    for (int mt = 0; mt < 2; mt++) {
        int r0 = mBase + wm * 32 + mt * 16 + (lane >> 2);
        #pragma unroll
        for (int half = 0; half < 2; half++) {
            int row = r0 + half * 8;
            int bb = row >> 11, ssi = row & 2047;
            #pragma unroll
            for (int nt = 0; nt < 4; nt++) {
                int colg = nBase + wn * 32 + nt * 8 + 2 * (lane & 3);
                int h = colg >> 6, dh = colg & 63;
                float* dst = Obuf + (((size_t)bb * Hh + h) * Ss + ssi) * DH + dh;
                *(float2*)dst = make_float2(
                    to_tf32(acc[mt][nt][half * 2 + 0] * scale),
                    to_tf32(acc[mt][nt][half * 2 + 1] * scale));
            }
        }
    }
}

// Output projection (1xtf32): plain fp32 store to d_out
__global__ __launch_bounds__(256, 3) void gemm_out_tf(float* __restrict__ C) {
    extern __shared__ char smc[];
    const int lane = threadIdx.x & 31, wid = threadIdx.x >> 5;
    const int wm = wid >> 1, wn = wid & 1;
    const int mBase = blockIdx.x * 128, nBase = blockIdx.y * 64;

    float acc[2][4][4];
    gemm_core_tf(g_Ot + (size_t)mBase * Dd, g_Wot + (size_t)nBase * Dd, smc, acc);

    #pragma unroll
    for (int mt = 0; mt < 2; mt++) {
        int r0 = mBase + wm * 32 + mt * 16 + (lane >> 2);
        #pragma unroll
        for (int half = 0; half < 2; half++) {
            int row = r0 + half * 8;
            float* dst = C + (size_t)row * Dd + nBase + wn * 32;
            #pragma unroll
            for (int nt = 0; nt < 4; nt++) {
                int d = nt * 8 + 2 * (lane & 3);
                *(float2*)(dst + d) = make_float2(acc[mt][nt][half * 2 + 0],
                                                  acc[mt][nt][half * 2 + 1]);
            }
        }
    }
}

// ============================================================================
// Flash attention, 128 threads, 4 warps x 32 rows, 2 CTAs/SM.
// NEW: K and V in separate commit groups; V's load latency hidden under
// S = QK^T + softmax compute (wait K -> compute S/P -> wait V -> PV).
// ============================================================================
#define QS_OFF 0
#define KS_OFF 8704
#define VS_OFF 13056
#define PS_OFF 17664

__global__ __launch_bounds__(128) void attn_mma() {
    extern __shared__ float sm[];
    float* Qs = sm + QS_OFF;
    float* Ks = sm + KS_OFF;
    float* Vs = sm + VS_OFF;
    float* Ps = sm + PS_OFF;

    const int tid = threadIdx.x;
    const int lane = tid & 31, wid = tid >> 5;
    const int qt = gridDim.x - 1 - blockIdx.x;
    const int h = blockIdx.y, b = blockIdx.z;

    const float* Qg = g_Q + (((size_t)b * Hh + h) * Ss + (size_t)qt * 128) * DH;
    const float* Kg = g_K + (((size_t)b * Hh + h) * Ss) * DH;
    const float* Vg = g_V + (((size_t)b * Hh + h) * Ss) * DH;

    uint32_t sQ = smem_u32(Qs), sK = smem_u32(Ks), sV = smem_u32(Vs);

    #pragma unroll
    for (int t = 0; t < 16; t++) {
        int idx = tid + t * 128;
        int r = idx >> 4, c = (idx & 15) * 4;
        cp16(sQ + (r * 68 + c) * 4, Qg + r * DH + c);
    }
    cp_commit();

    float o[2][8][4];
    float mrow[2][2], lrow[2][2];
    #pragma unroll
    for (int mt = 0; mt < 2; mt++) {
        mrow[mt][0] = mrow[mt][1] = -1e30f;
        lrow[mt][0] = lrow[mt][1] = 0.f;
        #pragma unroll
        for (int nt = 0; nt < 8; nt++)
            #pragma unroll
            for (int q = 0; q < 4; q++) o[mt][nt][q] = 0.f;
    }

    const int cL = lane & 3, rL = lane >> 2;
    const int ktMax = 2 * qt + 1;

    for (int kt = 0; kt <= ktMax; kt++) {
        __syncthreads();   // all warps done with prev iter's Ks/Vs
        const float* Kp = Kg + (size_t)kt * 64 * DH;
        const float* Vp = Vg + (size_t)kt * 64 * DH;
        // K: own commit group
        #pragma unroll
        for (int t = 0; t < 8; t++) {
            int idx = tid + t * 128;
            int r = idx >> 4, c = (idx & 15) * 4;
            cp16(sK + (r * 68 + c) * 4, Kp + r * DH + c);
        }
        cp_commit();
        // V: own commit group (stays in flight during S compute)
        #pragma unroll
        for (int t = 0; t < 8; t++) {
            int idx = tid + t * 128;
            int r = idx >> 4, c = (idx & 15) * 4;
            cp16(sV + (r * 72 + c) * 4, Vp + r * DH + c);
        }
        cp_commit();
        cp_wait1();        // K (and Q) resident; V may still be loading
        __syncthreads();

        float s[2][8][4];
        #pragma unroll
        for (int mt = 0; mt < 2; mt++)
            #pragma unroll
            for (int nt = 0; nt < 8; nt++)
                #pragma unroll
                for (int q = 0; q < 4; q++) s[mt][nt][q] = 0.f;

        #pragma unroll
        for (int ks = 0; ks < 8; ks++) {
            const int kb = ks * 8 + cL;
            uint32_t bfr[8][2];
            #pragma unroll
            for (int nt = 0; nt < 8; nt++) {
                const float* kp = Ks + (nt * 8 + rL) * 68;
                bfr[nt][0] = f2u(kp[kb]);
                bfr[nt][1] = f2u(kp[kb + 4]);
            }
            #pragma unroll
            for (int mt = 0; mt < 2; mt++) {
                const float* qp = Qs + (wid * 32 + mt * 16 + rL) * 68;
                uint32_t a[4];
                a[0] = f2u(qp[kb]);
                a[1] = f2u(qp[8 * 68 + kb]);
                a[2] = f2u(qp[kb + 4]);
                a[3] = f2u(qp[8 * 68 + kb + 4]);
                #pragma unroll
                for (int nt = 0; nt < 8; nt++) mma8(s[mt][nt], a, bfr[nt]);
            }
        }

        if (kt >= 2 * qt) {
            #pragma unroll
            for (int mt = 0; mt < 2; mt++) {
                int rg0 = qt * 128 + wid * 32 + mt * 16 + rL;
                #pragma unroll
                for (int nt = 0; nt < 8; nt++) {
                    int cg = kt * 64 + nt * 8 + 2 * cL;
                    if (cg     > rg0)     s[mt][nt][0] = -1e30f;
                    if (cg + 1 > rg0)     s[mt][nt][1] = -1e30f;
                    if (cg     > rg0 + 8) s[mt][nt][2] = -1e30f;
                    if (cg + 1 > rg0 + 8) s[mt][nt][3] = -1e30f;
                }
            }
        }

        #pragma unroll
        for (int mt = 0; mt < 2; mt++) {
            float v0 = -1e30f, v1 = -1e30f;
            #pragma unroll
            for (int nt = 0; nt < 8; nt++) {
                v0 = fmaxf(v0, fmaxf(s[mt][nt][0], s[mt][nt][1]));
                v1 = fmaxf(v1, fmaxf(s[mt][nt][2], s[mt][nt][3]));
            }
            v0 = fmaxf(v0, __shfl_xor_sync(0xffffffffu, v0, 1));
            v0 = fmaxf(v0, __shfl_xor_sync(0xffffffffu, v0, 2));
            v1 = fmaxf(v1, __shfl_xor_sync(0xffffffffu, v1, 1));
            v1 = fmaxf(v1, __shfl_xor_sync(0xffffffffu, v1, 2));

            float mn0 = fmaxf(mrow[mt][0], v0);
            float mn1 = fmaxf(mrow[mt][1], v1);
            float cr0 = __expf(mrow[mt][0] - mn0);
            float cr1 = __expf(mrow[mt][1] - mn1);
            mrow[mt][0] = mn0; mrow[mt][1] = mn1;

            float rs0 = 0.f, rs1 = 0.f;
            float* prow0 = Ps + (wid * 32 + mt * 16 + rL) * 72;
            float* prow1 = prow0 + 8 * 72;
            #pragma unroll
            for (int nt = 0; nt < 8; nt++) {
                float p0 = __expf(s[mt][nt][0] - mn0);
                float p1 = __expf(s[mt][nt][1] - mn0);
                float p2 = __expf(s[mt][nt][2] - mn1);
                float p3 = __expf(s[mt][nt][3] - mn1);
                rs0 += p0 + p1; rs1 += p2 + p3;
                int cc = nt * 8 + 2 * cL;
                *(float2*)(prow0 + cc) = make_float2(to_tf32(p0), to_tf32(p1));
                *(float2*)(prow1 + cc) = make_float2(to_tf32(p2), to_tf32(p3));
            }
            rs0 += __shfl_xor_sync(0xffffffffu, rs0, 1);
            rs0 += __shfl_xor_sync(0xffffffffu, rs0, 2);
            rs1 += __shfl_xor_sync(0xffffffffu, rs1, 1);
            rs1 += __shfl_xor_sync(0xffffffffu, rs1, 2);
            lrow[mt][0] = lrow[mt][0] * cr0 + rs0;
            lrow[mt][1] = lrow[mt][1] * cr1 + rs1;
            #pragma unroll
            for (int nt = 0; nt < 8; nt++) {
                o[mt][nt][0] *= cr0; o[mt][nt][1] *= cr0;
                o[mt][nt][2] *= cr1; o[mt][nt][3] *= cr1;
            }
        }

        cp_wait0();        // V resident (latency hidden behind S + softmax)
        __syncwarp();      // own warp's P rows visible before PV

        #pragma unroll
        for (int ks = 0; ks < 8; ks++) {
            const int kb = ks * 8;
            uint32_t bfr[8][2];
            #pragma unroll
            for (int nt = 0; nt < 8; nt++) {
                bfr[nt][0] = f2u(Vs[(kb + cL) * 72 + nt * 8 + rL]);
                bfr[nt][1] = f2u(Vs[(kb + 4 + cL) * 72 + nt * 8 + rL]);
            }
            #pragma unroll
            for (int mt = 0; mt < 2; mt++) {
                const float* pp = Ps + (wid * 32 + mt * 16 + rL) * 72;
                uint32_t a[4];
                a[0] = f2u(pp[kb + cL]);
                a[1] = f2u(pp[8 * 72 + kb + cL]);
                a[2] = f2u(pp[kb + 4 + cL]);
                a[3] = f2u(pp[8 * 72 + kb + 4 + cL]);
                #pragma unroll
                for (int nt = 0; nt < 8; nt++) mma8(o[mt][nt], a, bfr[nt]);
            }
        }
    }

    // epilogue: normalize, tf32-round, store fp32 to g_Ot [B*S, 768]
    #pragma unroll
    for (int mt = 0; mt < 2; mt++) {
        float inv0 = 1.f / lrow[mt][0];
        float inv1 = 1.f / lrow[mt][1];
        int r0 = qt * 128 + wid * 32 + mt * 16 + rL;
        size_t base0 = ((size_t)b * Ss + r0) * Dd + h * DH;
        size_t base1 = base0 + 8 * Dd;
        #pragma unroll
        for (int nt = 0; nt < 8; nt++) {
            int cc = nt * 8 + 2 * cL;
            *(float2*)(g_Ot + base0 + cc) = make_float2(to_tf32(o[mt][nt][0] * inv0),
                                                        to_tf32(o[mt][nt][1] * inv0));
            *(float2*)(g_Ot + base1 + cc) = make_float2(to_tf32(o[mt][nt][2] * inv1),
                                                        to_tf32(o[mt][nt][3] * inv1));
        }
    }
}

// ---------------------------------------------------------------------------

extern "C" void kernel_launch(void* const* d_in, const int* in_sizes, int n_in,
                              void* d_out, int out_size)
{
    const float* x  = (const float*)d_in[0];
    const float* Wq = (const float*)d_in[1];
    const float* Wk = (const float*)d_in[2];
    const float* Wv = (const float*)d_in[3];
    const float* Wo = (const float*)d_in[4];
    float* out = (float*)d_out;

    const int TF_SMEM   = 2 * TSTG_B;                          // 55296
    const int ATTN_SMEM = (PS_OFF + 128 * 72) * (int)sizeof(float);  // 107520

    cudaFuncSetAttribute(gemm_qkv_tf, cudaFuncAttributeMaxDynamicSharedMemorySize, TF_SMEM);
    cudaFuncSetAttribute(gemm_out_tf, cudaFuncAttributeMaxDynamicSharedMemorySize, TF_SMEM);
    cudaFuncSetAttribute(attn_mma,    cudaFuncAttributeMaxDynamicSharedMemorySize, ATTN_SMEM);

    conv_all<<<512, 256>>>(x, Wq, Wk, Wv, Wo);
    gemm_qkv_tf<<<dim3(Mm / 128, Dd / 64, 3), 256, TF_SMEM>>>();
    attn_mma<<<dim3(Ss / 128, Hh, Bb), 128, ATTN_SMEM>>>();
    gemm_out_tf<<<dim3(Mm / 128, Dd / 64), 256, TF_SMEM>>>(out);
}

// round 16
// speedup vs baseline: 1.2128x; 1.0496x over previous
#include <cuda_runtime.h>
#include <cuda_bf16.h>
#include <float.h>
#include <stdint.h>

#define Bb 2
#define Ss 2048
#define Dd 768
#define Hh 12
#define DH 64
#define Mm (Bb*Ss)

// ---------------- scratch ----------------
__device__ float g_Q[(size_t)Bb*Hh*Ss*DH];
__device__ float g_K[(size_t)Bb*Hh*Ss*DH];
__device__ float g_V[(size_t)Bb*Hh*Ss*DH];
__device__ float g_Ot[(size_t)Mm*Dd];              // attention out, tf32-rounded
__device__ float g_Xt[(size_t)Mm*Dd];              // tf32-rounded X
__device__ float g_Wt[3][(size_t)Dd*Dd];           // tf32-rounded Wq/Wk/Wv
__device__ float g_Wot[(size_t)Dd*Dd];             // tf32-rounded Wo
// split-KV partials: 2*12*5 tiles x 2 halves x 128 rows (x64 dims for O)
__device__ float g_Po[(size_t)240*128*64];
__device__ float g_Pm[(size_t)240*128];
__device__ float g_Pl[(size_t)240*128];

// work table: 21 items per (h,b), heavy-first.
// qt 0..10 unsplit; qt 11..15 split into half 0 ([0,qt+1)) and half 1 ([qt+1,2qt+2))
__device__ const int8_t d_wqt[21]   = {10,9,8,15,15,7,14,14,13,13,6,12,12,11,11,5,4,3,2,1,0};
__device__ const int8_t d_whalf[21] = {-1,-1,-1,0,1,-1,0,1,0,1,-1,0,1,0,1,-1,-1,-1,-1,-1,-1};

// ---------------- helpers ----------------
__device__ __forceinline__ uint32_t smem_u32(const void* p) {
    uint32_t a;
    asm("{ .reg .u64 t; cvta.to.shared.u64 t, %1; cvt.u32.u64 %0, t; }" : "=r"(a) : "l"(p));
    return a;
}
__device__ __forceinline__ void cp16(uint32_t dst, const void* src) {
    asm volatile("cp.async.cg.shared.global [%0], [%1], 16;"
        :: "r"(dst), "l"(__cvta_generic_to_global(src)));
}
__device__ __forceinline__ void cp_commit() { asm volatile("cp.async.commit_group;"); }
__device__ __forceinline__ void cp_wait0()  { asm volatile("cp.async.wait_group 0;"); }
__device__ __forceinline__ void cp_wait1()  { asm volatile("cp.async.wait_group 1;"); }

__device__ __forceinline__ float to_tf32(float x) {
    uint32_t u;
    asm("cvt.rna.tf32.f32 %0, %1;" : "=r"(u) : "f"(x));
    return __uint_as_float(u);
}
__device__ __forceinline__ uint32_t f2u(float x) { return __float_as_uint(x); }

__device__ __forceinline__ void mma8(float* d, const uint32_t* a, const uint32_t* b) {
    asm volatile("mma.sync.aligned.m16n8k8.row.col.f32.tf32.tf32.f32 "
        "{%0,%1,%2,%3}, {%4,%5,%6,%7}, {%8,%9}, {%0,%1,%2,%3};"
        : "+f"(d[0]), "+f"(d[1]), "+f"(d[2]), "+f"(d[3])
        : "r"(a[0]), "r"(a[1]), "r"(a[2]), "r"(a[3]), "r"(b[0]), "r"(b[1]));
}
__device__ __forceinline__ void ldm4(uint32_t* r, uint32_t addr) {
    asm volatile("ldmatrix.sync.aligned.m8n8.x4.shared.b16 {%0,%1,%2,%3}, [%4];"
        : "=r"(r[0]), "=r"(r[1]), "=r"(r[2]), "=r"(r[3]) : "r"(addr));
}

// ---------------- pre-pass ----------------
__global__ void conv_all(const float* __restrict__ x,
                         const float* __restrict__ wq, const float* __restrict__ wk,
                         const float* __restrict__ wv, const float* __restrict__ wo) {
    int i = blockIdx.x * blockDim.x + threadIdx.x;
    int stride = gridDim.x * blockDim.x;
    for (int t = i; t < Mm * Dd; t += stride) g_Xt[t] = to_tf32(x[t]);
    const float* ws[3] = {wq, wk, wv};
    for (int z = 0; z < 3; z++)
        for (int t = i; t < Dd * Dd; t += stride) g_Wt[z][t] = to_tf32(ws[z][t]);
    for (int t = i; t < Dd * Dd; t += stride) g_Wot[t] = to_tf32(wo[t]);
}

// ============================================================================
// 1xtf32 GEMM core (unchanged): CTA 128x64, BK=32, 2-stage, 3 CTAs/SM
// ============================================================================
#define TSTG_B 27648
#define TOFF_B 18432
#define GCH32 24

__device__ __forceinline__ void gemm_core_tf(const float* __restrict__ A,
                                             const float* __restrict__ B,
                                             char* smc, float acc[2][4][4]) {
    const int tid = threadIdx.x;
    const int lane = tid & 31;
    const int wid = tid >> 5;
    const int wm = wid >> 1, wn = wid & 1;

    uint32_t sb = smem_u32(smc);

    #pragma unroll
    for (int mt = 0; mt < 2; mt++)
        #pragma unroll
        for (int nt = 0; nt < 4; nt++)
            #pragma unroll
            for (int q = 0; q < 4; q++) acc[mt][nt][q] = 0.f;

    uint32_t soA[4]; size_t goA[4];
    #pragma unroll
    for (int t = 0; t < 4; t++) {
        int idx = t * 256 + tid;
        int r = idx >> 3, s = idx & 7;
        soA[t] = (uint32_t)(r * 144 + s * 16);
        goA[t] = (size_t)r * Dd + s * 4;
    }
    uint32_t soB[2]; size_t goB[2];
    #pragma unroll
    for (int t = 0; t < 2; t++) {
        int idx = t * 256 + tid;
        int r = idx >> 3, s = idx & 7;
        soB[t] = (uint32_t)(r * 144 + s * 16);
        goB[t] = (size_t)r * Dd + s * 4;
    }

    const int arow = ((lane >> 3) & 1) * 8 + (lane & 7);
    const uint32_t acolb = (uint32_t)((lane >> 4) * 16);
    const uint32_t aoff0 = (uint32_t)((wm * 32 + arow) * 144) + acolb;
    const uint32_t aoff1 = aoff0 + 16 * 144;
    const int brow = ((lane >> 4) << 3) + (lane & 7);
    const uint32_t bcolb = (uint32_t)(((lane >> 3) & 1) * 16);
    uint32_t boff[2];
    #pragma unroll
    for (int p = 0; p < 2; p++)
        boff[p] = (uint32_t)((wn * 32 + p * 16 + brow) * 144) + bcolb;

    auto load_chunk = [&](int c, int stage) {
        uint32_t st = sb + stage * TSTG_B;
        const size_t kq = (size_t)c * 32;
        #pragma unroll
        for (int t = 0; t < 4; t++) cp16(st + soA[t], A + goA[t] + kq);
        #pragma unroll
        for (int t = 0; t < 2; t++) cp16(st + TOFF_B + soB[t], B + goB[t] + kq);
        cp_commit();
    };

    load_chunk(0, 0);

    for (int c = 0; c < GCH32; c++) {
        cp_wait0();
        __syncthreads();
        if (c + 1 < GCH32) load_chunk(c + 1, (c + 1) & 1);

        const uint32_t st = sb + (c & 1) * TSTG_B;
        #pragma unroll
        for (int ks = 0; ks < 4; ks++) {
            const uint32_t kb = (uint32_t)(ks * 32);
            uint32_t a0[4], a1[4], b0[4], b1[4];
            ldm4(a0, st + aoff0 + kb);
            ldm4(a1, st + aoff1 + kb);
            ldm4(b0, st + TOFF_B + boff[0] + kb);
            ldm4(b1, st + TOFF_B + boff[1] + kb);
            mma8(acc[0][0], a0, b0);
            mma8(acc[1][0], a1, b0);
            mma8(acc[0][1], a0, b0 + 2);
            mma8(acc[1][1], a1, b0 + 2);
            mma8(acc[0][2], a0, b1);
            mma8(acc[1][2], a1, b1);
            mma8(acc[0][3], a0, b1 + 2);
            mma8(acc[1][3], a1, b1 + 2);
        }
    }
}

__global__ __launch_bounds__(256, 3) void gemm_qkv_tf() {
    extern __shared__ char smc[];
    const int lane = threadIdx.x & 31, wid = threadIdx.x >> 5;
    const int wm = wid >> 1, wn = wid & 1;
    const int z = blockIdx.z;
    const int mBase = blockIdx.x * 128, nBase = blockIdx.y * 64;

    float* Obuf = (z == 0) ? g_Q : (z == 1 ? g_K : g_V);
    const float scale = (z == 0) ? 0.125f : 1.0f;

    float acc[2][4][4];
    gemm_core_tf(g_Xt + (size_t)mBase * Dd, g_Wt[z] + (size_t)nBase * Dd, smc, acc);

    #pragma unroll
    for (int mt = 0; mt < 2; mt++) {
        int r0 = mBase + wm * 32 + mt * 16 + (lane >> 2);
        #pragma unroll
        for (int half = 0; half < 2; half++) {
            int row = r0 + half * 8;
            int bb = row >> 11, ssi = row & 2047;
            #pragma unroll
            for (int nt = 0; nt < 4; nt++) {
                int colg = nBase + wn * 32 + nt * 8 + 2 * (lane & 3);
                int h = colg >> 6, dh = colg & 63;
                float* dst = Obuf + (((size_t)bb * Hh + h) * Ss + ssi) * DH + dh;
                *(float2*)dst = make_float2(
                    to_tf32(acc[mt][nt][half * 2 + 0] * scale),
                    to_tf32(acc[mt][nt][half * 2 + 1] * scale));
            }
        }
    }
}

__global__ __launch_bounds__(256, 3) void gemm_out_tf(float* __restrict__ C) {
    extern __shared__ char smc[];
    const int lane = threadIdx.x & 31, wid = threadIdx.x >> 5;
    const int wm = wid >> 1, wn = wid & 1;
    const int mBase = blockIdx.x * 128, nBase = blockIdx.y * 64;

    float acc[2][4][4];
    gemm_core_tf(g_Ot + (size_t)mBase * Dd, g_Wot + (size_t)nBase * Dd, smc, acc);

    #pragma unroll
    for (int mt = 0; mt < 2; mt++) {
        int r0 = mBase + wm * 32 + mt * 16 + (lane >> 2);
        #pragma unroll
        for (int half = 0; half < 2; half++) {
            int row = r0 + half * 8;
            float* dst = C + (size_t)row * Dd + nBase + wn * 32;
            #pragma unroll
            for (int nt = 0; nt < 4; nt++) {
                int d = nt * 8 + 2 * (lane & 3);
                *(float2*)(dst + d) = make_float2(acc[mt][nt][half * 2 + 0],
                                                  acc[mt][nt][half * 2 + 1]);
            }
        }
    }
}

// ============================================================================
// Flash attention with split-KV work table.
// grid (Hh, Bb, 21): item z (slowest) heavy-first. 128 thr, 2 CTAs/SM.
// ============================================================================
#define QS_OFF 0
#define KS_OFF 8704
#define VS_OFF 13056
#define PS_OFF 17664

__global__ __launch_bounds__(128) void attn_mma() {
    extern __shared__ float sm[];
    float* Qs = sm + QS_OFF;
    float* Ks = sm + KS_OFF;
    float* Vs = sm + VS_OFF;
    float* Ps = sm + PS_OFF;

    const int tid = threadIdx.x;
    const int lane = tid & 31, wid = tid >> 5;
    const int h = blockIdx.x, b = blockIdx.y;
    const int item = blockIdx.z;
    const int qt = d_wqt[item];
    const int half = d_whalf[item];
    int kt_begin = 0, kt_end = 2 * qt + 2;
    if (half == 0) kt_end = qt + 1;
    else if (half == 1) kt_begin = qt + 1;

    const float* Qg = g_Q + (((size_t)b * Hh + h) * Ss + (size_t)qt * 128) * DH;
    const float* Kg = g_K + (((size_t)b * Hh + h) * Ss) * DH;
    const float* Vg = g_V + (((size_t)b * Hh + h) * Ss) * DH;

    uint32_t sQ = smem_u32(Qs), sK = smem_u32(Ks), sV = smem_u32(Vs);

    #pragma unroll
    for (int t = 0; t < 16; t++) {
        int idx = tid + t * 128;
        int r = idx >> 4, c = (idx & 15) * 4;
        cp16(sQ + (r * 68 + c) * 4, Qg + r * DH + c);
    }
    cp_commit();

    float o[2][8][4];
    float mrow[2][2], lrow[2][2];
    #pragma unroll
    for (int mt = 0; mt < 2; mt++) {
        mrow[mt][0] = mrow[mt][1] = -1e30f;
        lrow[mt][0] = lrow[mt][1] = 0.f;
        #pragma unroll
        for (int nt = 0; nt < 8; nt++)
            #pragma unroll
            for (int q = 0; q < 4; q++) o[mt][nt][q] = 0.f;
    }

    const int cL = lane & 3, rL = lane >> 2;

    for (int kt = kt_begin; kt < kt_end; kt++) {
        __syncthreads();
        const float* Kp = Kg + (size_t)kt * 64 * DH;
        const float* Vp = Vg + (size_t)kt * 64 * DH;
        #pragma unroll
        for (int t = 0; t < 8; t++) {
            int idx = tid + t * 128;
            int r = idx >> 4, c = (idx & 15) * 4;
            cp16(sK + (r * 68 + c) * 4, Kp + r * DH + c);
        }
        cp_commit();
        #pragma unroll
        for (int t = 0; t < 8; t++) {
            int idx = tid + t * 128;
            int r = idx >> 4, c = (idx & 15) * 4;
            cp16(sV + (r * 72 + c) * 4, Vp + r * DH + c);
        }
        cp_commit();
        cp_wait1();
        __syncthreads();

        float s[2][8][4];
        #pragma unroll
        for (int mt = 0; mt < 2; mt++)
            #pragma unroll
            for (int nt = 0; nt < 8; nt++)
                #pragma unroll
                for (int q = 0; q < 4; q++) s[mt][nt][q] = 0.f;

        #pragma unroll
        for (int ks = 0; ks < 8; ks++) {
            const int kb = ks * 8 + cL;
            uint32_t bfr[8][2];
            #pragma unroll
            for (int nt = 0; nt < 8; nt++) {
                const float* kp = Ks + (nt * 8 + rL) * 68;
                bfr[nt][0] = f2u(kp[kb]);
                bfr[nt][1] = f2u(kp[kb + 4]);
            }
            #pragma unroll
            for (int mt = 0; mt < 2; mt++) {
                const float* qp = Qs + (wid * 32 + mt * 16 + rL) * 68;
                uint32_t a[4];
                a[0] = f2u(qp[kb]);
                a[1] = f2u(qp[8 * 68 + kb]);
                a[2] = f2u(qp[kb + 4]);
                a[3] = f2u(qp[8 * 68 + kb + 4]);
                #pragma unroll
                for (int nt = 0; nt < 8; nt++) mma8(s[mt][nt], a, bfr[nt]);
            }
        }

        if (kt >= 2 * qt) {
            #pragma unroll
            for (int mt = 0; mt < 2; mt++) {
                int rg0 = qt * 128 + wid * 32 + mt * 16 + rL;
                #pragma unroll
                for (int nt = 0; nt < 8; nt++) {
                    int cg = kt * 64 + nt * 8 + 2 * cL;
                    if (cg     > rg0)     s[mt][nt][0] = -1e30f;
                    if (cg + 1 > rg0)     s[mt][nt][1] = -1e30f;
                    if (cg     > rg0 + 8) s[mt][nt][2] = -1e30f;
                    if (cg + 1 > rg0 + 8) s[mt][nt][3] = -1e30f;
                }
            }
        }

        #pragma unroll
        for (int mt = 0; mt < 2; mt++) {
            float v0 = -1e30f, v1 = -1e30f;
            #pragma unroll
            for (int nt = 0; nt < 8; nt++) {
                v0 = fmaxf(v0, fmaxf(s[mt][nt][0], s[mt][nt][1]));
                v1 = fmaxf(v1, fmaxf(s[mt][nt][2], s[mt][nt][3]));
            }
            v0 = fmaxf(v0, __shfl_xor_sync(0xffffffffu, v0, 1));
            v0 = fmaxf(v0, __shfl_xor_sync(0xffffffffu, v0, 2));
            v1 = fmaxf(v1, __shfl_xor_sync(0xffffffffu, v1, 1));
            v1 = fmaxf(v1, __shfl_xor_sync(0xffffffffu, v1, 2));

            float mn0 = fmaxf(mrow[mt][0], v0);
            float mn1 = fmaxf(mrow[mt][1], v1);
            float cr0 = __expf(mrow[mt][0] - mn0);
            float cr1 = __expf(mrow[mt][1] - mn1);
            mrow[mt][0] = mn0; mrow[mt][1] = mn1;

            float rs0 = 0.f, rs1 = 0.f;
            float* prow0 = Ps + (wid * 32 + mt * 16 + rL) * 72;
            float* prow1 = prow0 + 8 * 72;
            #pragma unroll
            for (int nt = 0; nt < 8; nt++) {
                float p0 = __expf(s[mt][nt][0] - mn0);
                float p1 = __expf(s[mt][nt][1] - mn0);
                float p2 = __expf(s[mt][nt][2] - mn1);
                float p3 = __expf(s[mt][nt][3] - mn1);
                rs0 += p0 + p1; rs1 += p2 + p3;
                int cc = nt * 8 + 2 * cL;
                *(float2*)(prow0 + cc) = make_float2(to_tf32(p0), to_tf32(p1));
                *(float2*)(prow1 + cc) = make_float2(to_tf32(p2), to_tf32(p3));
            }
            rs0 += __shfl_xor_sync(0xffffffffu, rs0, 1);
            rs0 += __shfl_xor_sync(0xffffffffu, rs0, 2);
            rs1 += __shfl_xor_sync(0xffffffffu, rs1, 1);
            rs1 += __shfl_xor_sync(0xffffffffu, rs1, 2);
            lrow[mt][0] = lrow[mt][0] * cr0 + rs0;
            lrow[mt][1] = lrow[mt][1] * cr1 + rs1;
            #pragma unroll
            for (int nt = 0; nt < 8; nt++) {
                o[mt][nt][0] *= cr0; o[mt][nt][1] *= cr0;
                o[mt][nt][2] *= cr1; o[mt][nt][3] *= cr1;
            }
        }

        cp_wait0();
        __syncwarp();

        #pragma unroll
        for (int ks = 0; ks < 8; ks++) {
            const int kb = ks * 8;
            uint32_t bfr[8][2];
            #pragma unroll
            for (int nt = 0; nt < 8; nt++) {
                bfr[nt][0] = f2u(Vs[(kb + cL) * 72 + nt * 8 + rL]);
                bfr[nt][1] = f2u(Vs[(kb + 4 + cL) * 72 + nt * 8 + rL]);
            }
            #pragma unroll
            for (int mt = 0; mt < 2; mt++) {
                const float* pp = Ps + (wid * 32 + mt * 16 + rL) * 72;
                uint32_t a[4];
                a[0] = f2u(pp[kb + cL]);
                a[1] = f2u(pp[8 * 72 + kb + cL]);
                a[2] = f2u(pp[kb + 4 + cL]);
                a[3] = f2u(pp[8 * 72 + kb + 4 + cL]);
                #pragma unroll
                for (int nt = 0; nt < 8; nt++) mma8(o[mt][nt], a, bfr[nt]);
            }
        }
    }

    if (half < 0) {
        // unsplit: normalize, tf32-round, store to g_Ot
        #pragma unroll
        for (int mt = 0; mt < 2; mt++) {
            float inv0 = 1.f / lrow[mt][0];
            float inv1 = 1.f / lrow[mt][1];
            int r0 = qt * 128 + wid * 32 + mt * 16 + rL;
            size_t base0 = ((size_t)b * Ss + r0) * Dd + h * DH;
            size_t base1 = base0 + 8 * Dd;
            #pragma unroll
            for (int nt = 0; nt < 8; nt++) {
                int cc = nt * 8 + 2 * cL;
                *(float2*)(g_Ot + base0 + cc) = make_float2(to_tf32(o[mt][nt][0] * inv0),
                                                            to_tf32(o[mt][nt][1] * inv0));
                *(float2*)(g_Ot + base1 + cc) = make_float2(to_tf32(o[mt][nt][2] * inv1),
                                                            to_tf32(o[mt][nt][3] * inv1));
            }
        }
    } else {
        // split: store unnormalized partials + m,l
        int qi = qt - 11;
        size_t slot = ((((size_t)b * Hh + h) * 5 + qi) * 2 + half);
        float* Po = g_Po + slot * 128 * 64;
        float* Pm = g_Pm + slot * 128;
        float* Pl = g_Pl + slot * 128;
        #pragma unroll
        for (int mt = 0; mt < 2; mt++) {
            int r0 = wid * 32 + mt * 16 + rL;
            int r1 = r0 + 8;
            if (cL == 0) {
                Pm[r0] = mrow[mt][0]; Pl[r0] = lrow[mt][0];
                Pm[r1] = mrow[mt][1]; Pl[r1] = lrow[mt][1];
            }
            #pragma unroll
            for (int nt = 0; nt < 8; nt++) {
                int cc = nt * 8 + 2 * cL;
                *(float2*)(Po + (size_t)r0 * 64 + cc) = make_float2(o[mt][nt][0], o[mt][nt][1]);
                *(float2*)(Po + (size_t)r1 * 64 + cc) = make_float2(o[mt][nt][2], o[mt][nt][3]);
            }
        }
    }
}

// merge split halves: 120 blocks x 128 threads
__global__ void attn_merge() {
    int t = blockIdx.x;             // ((b*Hh+h)*5 + qi)
    int qi = t % 5;
    int hh = (t / 5) % Hh;
    int bb = t / (5 * Hh);
    int qt = 11 + qi;
    int r = threadIdx.x;

    size_t s0 = ((size_t)t * 2 + 0) * 128 + r;
    size_t s1 = ((size_t)t * 2 + 1) * 128 + r;
    float m0 = g_Pm[s0], m1 = g_Pm[s1];
    float l0 = g_Pl[s0], l1 = g_Pl[s1];
    float m = fmaxf(m0, m1);
    float c0 = __expf(m0 - m), c1 = __expf(m1 - m);
    float inv = 1.f / (c0 * l0 + c1 * l1);
    const float* o0 = g_Po + s0 * 64;
    const float* o1 = g_Po + s1 * 64;
    float* dst = g_Ot + ((size_t)bb * Ss + qt * 128 + r) * Dd + hh * DH;
    #pragma unroll
    for (int d = 0; d < 64; d += 2) {
        float v0 = (c0 * o0[d]     + c1 * o1[d])     * inv;
        float v1 = (c0 * o0[d + 1] + c1 * o1[d + 1]) * inv;
        *(float2*)(dst + d) = make_float2(to_tf32(v0), to_tf32(v1));
    }
}

// ---------------------------------------------------------------------------

extern "C" void kernel_launch(void* const* d_in, const int* in_sizes, int n_in,
                              void* d_out, int out_size)
{
    const float* x  = (const float*)d_in[0];
    const float* Wq = (const float*)d_in[1];
    const float* Wk = (const float*)d_in[2];
    const float* Wv = (const float*)d_in[3];
    const float* Wo = (const float*)d_in[4];
    float* out = (float*)d_out;

    const int TF_SMEM   = 2 * TSTG_B;                          // 55296
    const int ATTN_SMEM = (PS_OFF + 128 * 72) * (int)sizeof(float);  // 107520

    cudaFuncSetAttribute(gemm_qkv_tf, cudaFuncAttributeMaxDynamicSharedMemorySize, TF_SMEM);
    cudaFuncSetAttribute(gemm_out_tf, cudaFuncAttributeMaxDynamicSharedMemorySize, TF_SMEM);
    cudaFuncSetAttribute(attn_mma,    cudaFuncAttributeMaxDynamicSharedMemorySize, ATTN_SMEM);

    conv_all<<<512, 256>>>(x, Wq, Wk, Wv, Wo);
    gemm_qkv_tf<<<dim3(Mm / 128, Dd / 64, 3), 256, TF_SMEM>>>();
    attn_mma<<<dim3(Hh, Bb, 21), 128, ATTN_SMEM>>>();
    attn_merge<<<120, 128>>>();
    gemm_out_tf<<<dim3(Mm / 128, Dd / 64), 256, TF_SMEM>>>(out);
}

// round 17
// speedup vs baseline: 1.2852x; 1.0597x over previous
#include <cuda_runtime.h>
#include <cuda_bf16.h>
#include <float.h>
#include <stdint.h>

#define Bb 2
#define Ss 2048
#define Dd 768
#define Hh 12
#define DH 64
#define Mm (Bb*Ss)

// ---------------- scratch ----------------
__device__ float g_Q[(size_t)Bb*Hh*Ss*DH];
__device__ float g_K[(size_t)Bb*Hh*Ss*DH];
__device__ float g_V[(size_t)Bb*Hh*Ss*DH];
__device__ float g_Ot[(size_t)Mm*Dd];              // attention out, tf32-rounded
__device__ float g_Xt[(size_t)Mm*Dd];              // tf32-rounded X
__device__ float g_Wt[3][(size_t)Dd*Dd];           // tf32-rounded Wq/Wk/Wv
__device__ float g_Wot[(size_t)Dd*Dd];             // tf32-rounded Wo
// split-KV partials: 2*12*5 tiles x 2 halves x 128 rows (x64 dims for O)
__device__ float g_Po[(size_t)240*128*64];
__device__ float g_Pm[(size_t)240*128];
__device__ float g_Pl[(size_t)240*128];

// work table: 21 items per (h,b), heavy-first.
// qt 0..10 unsplit; qt 11..15 split into half 0 ([0,qt+1)) and half 1 ([qt+1,2qt+2))
__device__ const int8_t d_wqt[21]   = {10,9,8,15,15,7,14,14,13,13,6,12,12,11,11,5,4,3,2,1,0};
__device__ const int8_t d_whalf[21] = {-1,-1,-1,0,1,-1,0,1,0,1,-1,0,1,0,1,-1,-1,-1,-1,-1,-1};

// ---------------- helpers ----------------
__device__ __forceinline__ uint32_t smem_u32(const void* p) {
    uint32_t a;
    asm("{ .reg .u64 t; cvta.to.shared.u64 t, %1; cvt.u32.u64 %0, t; }" : "=r"(a) : "l"(p));
    return a;
}
__device__ __forceinline__ void cp16(uint32_t dst, const void* src) {
    asm volatile("cp.async.cg.shared.global [%0], [%1], 16;"
        :: "r"(dst), "l"(__cvta_generic_to_global(src)));
}
__device__ __forceinline__ void cp_commit() { asm volatile("cp.async.commit_group;"); }
__device__ __forceinline__ void cp_wait0()  { asm volatile("cp.async.wait_group 0;"); }
__device__ __forceinline__ void cp_wait1()  { asm volatile("cp.async.wait_group 1;"); }

__device__ __forceinline__ float to_tf32(float x) {
    uint32_t u;
    asm("cvt.rna.tf32.f32 %0, %1;" : "=r"(u) : "f"(x));
    return __uint_as_float(u);
}
__device__ __forceinline__ uint32_t f2u(float x) { return __float_as_uint(x); }

__device__ __forceinline__ void mma8(float* d, const uint32_t* a, const uint32_t* b) {
    asm volatile("mma.sync.aligned.m16n8k8.row.col.f32.tf32.tf32.f32 "
        "{%0,%1,%2,%3}, {%4,%5,%6,%7}, {%8,%9}, {%0,%1,%2,%3};"
        : "+f"(d[0]), "+f"(d[1]), "+f"(d[2]), "+f"(d[3])
        : "r"(a[0]), "r"(a[1]), "r"(a[2]), "r"(a[3]), "r"(b[0]), "r"(b[1]));
}
__device__ __forceinline__ void ldm4(uint32_t* r, uint32_t addr) {
    asm volatile("ldmatrix.sync.aligned.m8n8.x4.shared.b16 {%0,%1,%2,%3}, [%4];"
        : "=r"(r[0]), "=r"(r[1]), "=r"(r[2]), "=r"(r[3]) : "r"(addr));
}

// ---------------- pre-pass ----------------
__global__ void conv_all(const float* __restrict__ x,
                         const float* __restrict__ wq, const float* __restrict__ wk,
                         const float* __restrict__ wv, const float* __restrict__ wo) {
    int i = blockIdx.x * blockDim.x + threadIdx.x;
    int stride = gridDim.x * blockDim.x;
    for (int t = i; t < Mm * Dd; t += stride) g_Xt[t] = to_tf32(x[t]);
    const float* ws[3] = {wq, wk, wv};
    for (int z = 0; z < 3; z++)
        for (int t = i; t < Dd * Dd; t += stride) g_Wt[z][t] = to_tf32(ws[z][t]);
    for (int t = i; t < Dd * Dd; t += stride) g_Wot[t] = to_tf32(wo[t]);
}

// ============================================================================
// 1xtf32 GEMM core (unchanged): CTA 128x64, BK=32, 2-stage, 3 CTAs/SM
// ============================================================================
#define TSTG_B 27648
#define TOFF_B 18432
#define GCH32 24

__device__ __forceinline__ void gemm_core_tf(const float* __restrict__ A,
                                             const float* __restrict__ B,
                                             char* smc, float acc[2][4][4]) {
    const int tid = threadIdx.x;
    const int lane = tid & 31;
    const int wid = tid >> 5;
    const int wm = wid >> 1, wn = wid & 1;

    uint32_t sb = smem_u32(smc);

    #pragma unroll
    for (int mt = 0; mt < 2; mt++)
        #pragma unroll
        for (int nt = 0; nt < 4; nt++)
            #pragma unroll
            for (int q = 0; q < 4; q++) acc[mt][nt][q] = 0.f;

    uint32_t soA[4]; size_t goA[4];
    #pragma unroll
    for (int t = 0; t < 4; t++) {
        int idx = t * 256 + tid;
        int r = idx >> 3, s = idx & 7;
        soA[t] = (uint32_t)(r * 144 + s * 16);
        goA[t] = (size_t)r * Dd + s * 4;
    }
    uint32_t soB[2]; size_t goB[2];
    #pragma unroll
    for (int t = 0; t < 2; t++) {
        int idx = t * 256 + tid;
        int r = idx >> 3, s = idx & 7;
        soB[t] = (uint32_t)(r * 144 + s * 16);
        goB[t] = (size_t)r * Dd + s * 4;
    }

    const int arow = ((lane >> 3) & 1) * 8 + (lane & 7);
    const uint32_t acolb = (uint32_t)((lane >> 4) * 16);
    const uint32_t aoff0 = (uint32_t)((wm * 32 + arow) * 144) + acolb;
    const uint32_t aoff1 = aoff0 + 16 * 144;
    const int brow = ((lane >> 4) << 3) + (lane & 7);
    const uint32_t bcolb = (uint32_t)(((lane >> 3) & 1) * 16);
    uint32_t boff[2];
    #pragma unroll
    for (int p = 0; p < 2; p++)
        boff[p] = (uint32_t)((wn * 32 + p * 16 + brow) * 144) + bcolb;

    auto load_chunk = [&](int c, int stage) {
        uint32_t st = sb + stage * TSTG_B;
        const size_t kq = (size_t)c * 32;
        #pragma unroll
        for (int t = 0; t < 4; t++) cp16(st + soA[t], A + goA[t] + kq);
        #pragma unroll
        for (int t = 0; t < 2; t++) cp16(st + TOFF_B + soB[t], B + goB[t] + kq);
        cp_commit();
    };

    load_chunk(0, 0);

    for (int c = 0; c < GCH32; c++) {
        cp_wait0();
        __syncthreads();
        if (c + 1 < GCH32) load_chunk(c + 1, (c + 1) & 1);

        const uint32_t st = sb + (c & 1) * TSTG_B;
        #pragma unroll
        for (int ks = 0; ks < 4; ks++) {
            const uint32_t kb = (uint32_t)(ks * 32);
            uint32_t a0[4], a1[4], b0[4], b1[4];
            ldm4(a0, st + aoff0 + kb);
            ldm4(a1, st + aoff1 + kb);
            ldm4(b0, st + TOFF_B + boff[0] + kb);
            ldm4(b1, st + TOFF_B + boff[1] + kb);
            mma8(acc[0][0], a0, b0);
            mma8(acc[1][0], a1, b0);
            mma8(acc[0][1], a0, b0 + 2);
            mma8(acc[1][1], a1, b0 + 2);
            mma8(acc[0][2], a0, b1);
            mma8(acc[1][2], a1, b1);
            mma8(acc[0][3], a0, b1 + 2);
            mma8(acc[1][3], a1, b1 + 2);
        }
    }
}

__global__ __launch_bounds__(256, 3) void gemm_qkv_tf() {
    extern __shared__ char smc[];
    const int lane = threadIdx.x & 31, wid = threadIdx.x >> 5;
    const int wm = wid >> 1, wn = wid & 1;
    const int z = blockIdx.z;
    const int mBase = blockIdx.x * 128, nBase = blockIdx.y * 64;

    float* Obuf = (z == 0) ? g_Q : (z == 1 ? g_K : g_V);
    const float scale = (z == 0) ? 0.125f : 1.0f;

    float acc[2][4][4];
    gemm_core_tf(g_Xt + (size_t)mBase * Dd, g_Wt[z] + (size_t)nBase * Dd, smc, acc);

    #pragma unroll
    for (int mt = 0; mt < 2; mt++) {
        int r0 = mBase + wm * 32 + mt * 16 + (lane >> 2);
        #pragma unroll
        for (int half = 0; half < 2; half++) {
            int row = r0 + half * 8;
            int bb = row >> 11, ssi = row & 2047;
            #pragma unroll
            for (int nt = 0; nt < 4; nt++) {
                int colg = nBase + wn * 32 + nt * 8 + 2 * (lane & 3);
                int h = colg >> 6, dh = colg & 63;
                float* dst = Obuf + (((size_t)bb * Hh + h) * Ss + ssi) * DH + dh;
                *(float2*)dst = make_float2(
                    to_tf32(acc[mt][nt][half * 2 + 0] * scale),
                    to_tf32(acc[mt][nt][half * 2 + 1] * scale));
            }
        }
    }
}

__global__ __launch_bounds__(256, 3) void gemm_out_tf(float* __restrict__ C) {
    extern __shared__ char smc[];
    const int lane = threadIdx.x & 31, wid = threadIdx.x >> 5;
    const int wm = wid >> 1, wn = wid & 1;
    const int mBase = blockIdx.x * 128, nBase = blockIdx.y * 64;

    float acc[2][4][4];
    gemm_core_tf(g_Ot + (size_t)mBase * Dd, g_Wot + (size_t)nBase * Dd, smc, acc);

    #pragma unroll
    for (int mt = 0; mt < 2; mt++) {
        int r0 = mBase + wm * 32 + mt * 16 + (lane >> 2);
        #pragma unroll
        for (int half = 0; half < 2; half++) {
            int row = r0 + half * 8;
            float* dst = C + (size_t)row * Dd + nBase + wn * 32;
            #pragma unroll
            for (int nt = 0; nt < 4; nt++) {
                int d = nt * 8 + 2 * (lane & 3);
                *(float2*)(dst + d) = make_float2(acc[mt][nt][half * 2 + 0],
                                                  acc[mt][nt][half * 2 + 1]);
            }
        }
    }
}

// ============================================================================
// Flash attention with split-KV work table (unchanged from R16).
// grid (Hh, Bb, 21): item z (slowest) heavy-first. 128 thr, 2 CTAs/SM.
// ============================================================================
#define QS_OFF 0
#define KS_OFF 8704
#define VS_OFF 13056
#define PS_OFF 17664

__global__ __launch_bounds__(128) void attn_mma() {
    extern __shared__ float sm[];
    float* Qs = sm + QS_OFF;
    float* Ks = sm + KS_OFF;
    float* Vs = sm + VS_OFF;
    float* Ps = sm + PS_OFF;

    const int tid = threadIdx.x;
    const int lane = tid & 31, wid = tid >> 5;
    const int h = blockIdx.x, b = blockIdx.y;
    const int item = blockIdx.z;
    const int qt = d_wqt[item];
    const int half = d_whalf[item];
    int kt_begin = 0, kt_end = 2 * qt + 2;
    if (half == 0) kt_end = qt + 1;
    else if (half == 1) kt_begin = qt + 1;

    const float* Qg = g_Q + (((size_t)b * Hh + h) * Ss + (size_t)qt * 128) * DH;
    const float* Kg = g_K + (((size_t)b * Hh + h) * Ss) * DH;
    const float* Vg = g_V + (((size_t)b * Hh + h) * Ss) * DH;

    uint32_t sQ = smem_u32(Qs), sK = smem_u32(Ks), sV = smem_u32(Vs);

    #pragma unroll
    for (int t = 0; t < 16; t++) {
        int idx = tid + t * 128;
        int r = idx >> 4, c = (idx & 15) * 4;
        cp16(sQ + (r * 68 + c) * 4, Qg + r * DH + c);
    }
    cp_commit();

    float o[2][8][4];
    float mrow[2][2], lrow[2][2];
    #pragma unroll
    for (int mt = 0; mt < 2; mt++) {
        mrow[mt][0] = mrow[mt][1] = -1e30f;
        lrow[mt][0] = lrow[mt][1] = 0.f;
        #pragma unroll
        for (int nt = 0; nt < 8; nt++)
            #pragma unroll
            for (int q = 0; q < 4; q++) o[mt][nt][q] = 0.f;
    }

    const int cL = lane & 3, rL = lane >> 2;

    for (int kt = kt_begin; kt < kt_end; kt++) {
        __syncthreads();
        const float* Kp = Kg + (size_t)kt * 64 * DH;
        const float* Vp = Vg + (size_t)kt * 64 * DH;
        #pragma unroll
        for (int t = 0; t < 8; t++) {
            int idx = tid + t * 128;
            int r = idx >> 4, c = (idx & 15) * 4;
            cp16(sK + (r * 68 + c) * 4, Kp + r * DH + c);
        }
        cp_commit();
        #pragma unroll
        for (int t = 0; t < 8; t++) {
            int idx = tid + t * 128;
            int r = idx >> 4, c = (idx & 15) * 4;
            cp16(sV + (r * 72 + c) * 4, Vp + r * DH + c);
        }
        cp_commit();
        cp_wait1();
        __syncthreads();

        float s[2][8][4];
        #pragma unroll
        for (int mt = 0; mt < 2; mt++)
            #pragma unroll
            for (int nt = 0; nt < 8; nt++)
                #pragma unroll
                for (int q = 0; q < 4; q++) s[mt][nt][q] = 0.f;

        #pragma unroll
        for (int ks = 0; ks < 8; ks++) {
            const int kb = ks * 8 + cL;
            uint32_t bfr[8][2];
            #pragma unroll
            for (int nt = 0; nt < 8; nt++) {
                const float* kp = Ks + (nt * 8 + rL) * 68;
                bfr[nt][0] = f2u(kp[kb]);
                bfr[nt][1] = f2u(kp[kb + 4]);
            }
            #pragma unroll
            for (int mt = 0; mt < 2; mt++) {
                const float* qp = Qs + (wid * 32 + mt * 16 + rL) * 68;
                uint32_t a[4];
                a[0] = f2u(qp[kb]);
                a[1] = f2u(qp[8 * 68 + kb]);
                a[2] = f2u(qp[kb + 4]);
                a[3] = f2u(qp[8 * 68 + kb + 4]);
                #pragma unroll
                for (int nt = 0; nt < 8; nt++) mma8(s[mt][nt], a, bfr[nt]);
            }
        }

        if (kt >= 2 * qt) {
            #pragma unroll
            for (int mt = 0; mt < 2; mt++) {
                int rg0 = qt * 128 + wid * 32 + mt * 16 + rL;
                #pragma unroll
                for (int nt = 0; nt < 8; nt++) {
                    int cg = kt * 64 + nt * 8 + 2 * cL;
                    if (cg     > rg0)     s[mt][nt][0] = -1e30f;
                    if (cg + 1 > rg0)     s[mt][nt][1] = -1e30f;
                    if (cg     > rg0 + 8) s[mt][nt][2] = -1e30f;
                    if (cg + 1 > rg0 + 8) s[mt][nt][3] = -1e30f;
                }
            }
        }

        #pragma unroll
        for (int mt = 0; mt < 2; mt++) {
            float v0 = -1e30f, v1 = -1e30f;
            #pragma unroll
            for (int nt = 0; nt < 8; nt++) {
                v0 = fmaxf(v0, fmaxf(s[mt][nt][0], s[mt][nt][1]));
                v1 = fmaxf(v1, fmaxf(s[mt][nt][2], s[mt][nt][3]));
            }
            v0 = fmaxf(v0, __shfl_xor_sync(0xffffffffu, v0, 1));
            v0 = fmaxf(v0, __shfl_xor_sync(0xffffffffu, v0, 2));
            v1 = fmaxf(v1, __shfl_xor_sync(0xffffffffu, v1, 1));
            v1 = fmaxf(v1, __shfl_xor_sync(0xffffffffu, v1, 2));

            float mn0 = fmaxf(mrow[mt][0], v0);
            float mn1 = fmaxf(mrow[mt][1], v1);
            float cr0 = __expf(mrow[mt][0] - mn0);
            float cr1 = __expf(mrow[mt][1] - mn1);
            mrow[mt][0] = mn0; mrow[mt][1] = mn1;

            float rs0 = 0.f, rs1 = 0.f;
            float* prow0 = Ps + (wid * 32 + mt * 16 + rL) * 72;
            float* prow1 = prow0 + 8 * 72;
            #pragma unroll
            for (int nt = 0; nt < 8; nt++) {
                float p0 = __expf(s[mt][nt][0] - mn0);
                float p1 = __expf(s[mt][nt][1] - mn0);
                float p2 = __expf(s[mt][nt][2] - mn1);
                float p3 = __expf(s[mt][nt][3] - mn1);
                rs0 += p0 + p1; rs1 += p2 + p3;
                int cc = nt * 8 + 2 * cL;
                *(float2*)(prow0 + cc) = make_float2(to_tf32(p0), to_tf32(p1));
                *(float2*)(prow1 + cc) = make_float2(to_tf32(p2), to_tf32(p3));
            }
            rs0 += __shfl_xor_sync(0xffffffffu, rs0, 1);
            rs0 += __shfl_xor_sync(0xffffffffu, rs0, 2);
            rs1 += __shfl_xor_sync(0xffffffffu, rs1, 1);
            rs1 += __shfl_xor_sync(0xffffffffu, rs1, 2);
            lrow[mt][0] = lrow[mt][0] * cr0 + rs0;
            lrow[mt][1] = lrow[mt][1] * cr1 + rs1;
            #pragma unroll
            for (int nt = 0; nt < 8; nt++) {
                o[mt][nt][0] *= cr0; o[mt][nt][1] *= cr0;
                o[mt][nt][2] *= cr1; o[mt][nt][3] *= cr1;
            }
        }

        cp_wait0();
        __syncwarp();

        #pragma unroll
        for (int ks = 0; ks < 8; ks++) {
            const int kb = ks * 8;
            uint32_t bfr[8][2];
            #pragma unroll
            for (int nt = 0; nt < 8; nt++) {
                bfr[nt][0] = f2u(Vs[(kb + cL) * 72 + nt * 8 + rL]);
                bfr[nt][1] = f2u(Vs[(kb + 4 + cL) * 72 + nt * 8 + rL]);
            }
            #pragma unroll
            for (int mt = 0; mt < 2; mt++) {
                const float* pp = Ps + (wid * 32 + mt * 16 + rL) * 72;
                uint32_t a[4];
                a[0] = f2u(pp[kb + cL]);
                a[1] = f2u(pp[8 * 72 + kb + cL]);
                a[2] = f2u(pp[kb + 4 + cL]);
                a[3] = f2u(pp[8 * 72 + kb + 4 + cL]);
                #pragma unroll
                for (int nt = 0; nt < 8; nt++) mma8(o[mt][nt], a, bfr[nt]);
            }
        }
    }

    if (half < 0) {
        #pragma unroll
        for (int mt = 0; mt < 2; mt++) {
            float inv0 = 1.f / lrow[mt][0];
            float inv1 = 1.f / lrow[mt][1];
            int r0 = qt * 128 + wid * 32 + mt * 16 + rL;
            size_t base0 = ((size_t)b * Ss + r0) * Dd + h * DH;
            size_t base1 = base0 + 8 * Dd;
            #pragma unroll
            for (int nt = 0; nt < 8; nt++) {
                int cc = nt * 8 + 2 * cL;
                *(float2*)(g_Ot + base0 + cc) = make_float2(to_tf32(o[mt][nt][0] * inv0),
                                                            to_tf32(o[mt][nt][1] * inv0));
                *(float2*)(g_Ot + base1 + cc) = make_float2(to_tf32(o[mt][nt][2] * inv1),
                                                            to_tf32(o[mt][nt][3] * inv1));
            }
        }
    } else {
        int qi = qt - 11;
        size_t slot = ((((size_t)b * Hh + h) * 5 + qi) * 2 + half);
        float* Po = g_Po + slot * 128 * 64;
        float* Pm = g_Pm + slot * 128;
        float* Pl = g_Pl + slot * 128;
        #pragma unroll
        for (int mt = 0; mt < 2; mt++) {
            int r0 = wid * 32 + mt * 16 + rL;
            int r1 = r0 + 8;
            if (cL == 0) {
                Pm[r0] = mrow[mt][0]; Pl[r0] = lrow[mt][0];
                Pm[r1] = mrow[mt][1]; Pl[r1] = lrow[mt][1];
            }
            #pragma unroll
            for (int nt = 0; nt < 8; nt++) {
                int cc = nt * 8 + 2 * cL;
                *(float2*)(Po + (size_t)r0 * 64 + cc) = make_float2(o[mt][nt][0], o[mt][nt][1]);
                *(float2*)(Po + (size_t)r1 * 64 + cc) = make_float2(o[mt][nt][2], o[mt][nt][3]);
            }
        }
    }
}

// merge split halves: one float4 per thread (120 tiles x 128 rows x 16 float4)
__global__ __launch_bounds__(256) void attn_merge() {
    int idx = blockIdx.x * 256 + threadIdx.x;      // 0 .. 245759
    int dq = idx & 15;                             // float4 index within 64 dims
    int r  = (idx >> 4) & 127;
    int t  = idx >> 11;                            // tile 0..119
    if (t >= 120) return;

    int qi = t % 5;
    int hh = (t / 5) % Hh;
    int bb = t / (5 * Hh);
    int qt = 11 + qi;

    size_t s0 = ((size_t)t * 2 + 0) * 128 + r;
    size_t s1 = ((size_t)t * 2 + 1) * 128 + r;
    float m0 = g_Pm[s0], m1 = g_Pm[s1];
    float l0 = g_Pl[s0], l1 = g_Pl[s1];
    float m = fmaxf(m0, m1);
    float c0 = __expf(m0 - m), c1 = __expf(m1 - m);
    float inv = 1.f / (c0 * l0 + c1 * l1);

    float4 a = *(const float4*)(g_Po + s0 * 64 + dq * 4);
    float4 bq = *(const float4*)(g_Po + s1 * 64 + dq * 4);
    float4 v;
    v.x = to_tf32((c0 * a.x + c1 * bq.x) * inv);
    v.y = to_tf32((c0 * a.y + c1 * bq.y) * inv);
    v.z = to_tf32((c0 * a.z + c1 * bq.z) * inv);
    v.w = to_tf32((c0 * a.w + c1 * bq.w) * inv);

    float* dst = g_Ot + ((size_t)bb * Ss + qt * 128 + r) * Dd + hh * DH + dq * 4;
    *(float4*)dst = v;
}

// ---------------------------------------------------------------------------

extern "C" void kernel_launch(void* const* d_in, const int* in_sizes, int n_in,
                              void* d_out, int out_size)
{
    const float* x  = (const float*)d_in[0];
    const float* Wq = (const float*)d_in[1];
    const float* Wk = (const float*)d_in[2];
    const float* Wv = (const float*)d_in[3];
    const float* Wo = (const float*)d_in[4];
    float* out = (float*)d_out;

    const int TF_SMEM   = 2 * TSTG_B;                          // 55296
    const int ATTN_SMEM = (PS_OFF + 128 * 72) * (int)sizeof(float);  // 107520

    cudaFuncSetAttribute(gemm_qkv_tf, cudaFuncAttributeMaxDynamicSharedMemorySize, TF_SMEM);
    cudaFuncSetAttribute(gemm_out_tf, cudaFuncAttributeMaxDynamicSharedMemorySize, TF_SMEM);
    cudaFuncSetAttribute(attn_mma,    cudaFuncAttributeMaxDynamicSharedMemorySize, ATTN_SMEM);

    conv_all<<<512, 256>>>(x, Wq, Wk, Wv, Wo);
    gemm_qkv_tf<<<dim3(Mm / 128, Dd / 64, 3), 256, TF_SMEM>>>();
    attn_mma<<<dim3(Hh, Bb, 21), 128, ATTN_SMEM>>>();
    attn_merge<<<960, 256>>>();
    gemm_out_tf<<<dim3(Mm / 128, Dd / 64), 256, TF_SMEM>>>(out);
}